// round 10
// baseline (speedup 1.0000x reference)
#include <cuda_runtime.h>
#include <cuda_bf16.h>
#include <math.h>
#include <stdint.h>

#define B_  2
#define S_  2048
#define D_  1024
#define H_  16
#define DK_ 64
#define MROWS (B_*S_)      // 4096

// ---------------- scratch (allocation-free: __device__ globals) -------------
__device__ __nv_bfloat16 g_qh[MROWS*D_];
__device__ __nv_bfloat16 g_ql[MROWS*D_];
__device__ __nv_bfloat16 g_kh[MROWS*D_];
__device__ __nv_bfloat16 g_kl[MROWS*D_];
__device__ __nv_bfloat16 g_vh[MROWS*D_];
__device__ __nv_bfloat16 g_vl[MROWS*D_];
__device__ __nv_bfloat16 g_chi[MROWS*D_];
__device__ __nv_bfloat16 g_clo[MROWS*D_];
__device__ __nv_bfloat16 g_xhi[MROWS*D_];
__device__ __nv_bfloat16 g_xlo[MROWS*D_];
__device__ __nv_bfloat16 g_wthi[4*D_*D_];   // transposed weights [N,K], contiguous => [4096,1024]
__device__ __nv_bfloat16 g_wtlo[4*D_*D_];
__device__ float g_vsum[B_*H_*DK_];

// ======================= helpers =============================================
__device__ __forceinline__ uint32_t smem_u32(const void* p) {
    uint32_t a;
    asm("{ .reg .u64 t; cvta.to.shared.u64 t, %1; cvt.u32.u64 %0, t; }"
        : "=r"(a) : "l"(p));
    return a;
}
__device__ __forceinline__ void ldsm_x4(uint32_t* r, uint32_t addr) {
    asm volatile("ldmatrix.sync.aligned.m8n8.x4.shared.b16 {%0,%1,%2,%3}, [%4];"
                 : "=r"(r[0]), "=r"(r[1]), "=r"(r[2]), "=r"(r[3]) : "r"(addr));
}
__device__ __forceinline__ void ldsm_x4_t(uint32_t* r, uint32_t addr) {
    asm volatile("ldmatrix.sync.aligned.m8n8.x4.trans.shared.b16 {%0,%1,%2,%3}, [%4];"
                 : "=r"(r[0]), "=r"(r[1]), "=r"(r[2]), "=r"(r[3]) : "r"(addr));
}
__device__ __forceinline__ void mma16816(float* c, const uint32_t* a, const uint32_t* b) {
    asm volatile("mma.sync.aligned.m16n8k16.row.col.f32.bf16.bf16.f32 "
                 "{%0,%1,%2,%3}, {%4,%5,%6,%7}, {%8,%9}, {%0,%1,%2,%3};"
                 : "+f"(c[0]), "+f"(c[1]), "+f"(c[2]), "+f"(c[3])
                 : "r"(a[0]), "r"(a[1]), "r"(a[2]), "r"(a[3]),
                   "r"(b[0]), "r"(b[1]));
}
__device__ __forceinline__ uint32_t pack_bf16x2(float a, float b) {
    __nv_bfloat162 t = __floats2bfloat162_rn(a, b);
    return *(uint32_t*)&t;
}

// ======================= preprocessing kernels ==============================
__global__ void split_kernel(const float* __restrict__ src,
                             __nv_bfloat16* __restrict__ hi,
                             __nv_bfloat16* __restrict__ lo) {
    int i = blockIdx.x * blockDim.x + threadIdx.x;
    float4 v = ((const float4*)src)[i];
    __nv_bfloat16 h0 = __float2bfloat16(v.x), h1 = __float2bfloat16(v.y);
    __nv_bfloat16 h2 = __float2bfloat16(v.z), h3 = __float2bfloat16(v.w);
    __nv_bfloat16 l0 = __float2bfloat16(v.x - __bfloat162float(h0));
    __nv_bfloat16 l1 = __float2bfloat16(v.y - __bfloat162float(h1));
    __nv_bfloat16 l2 = __float2bfloat16(v.z - __bfloat162float(h2));
    __nv_bfloat16 l3 = __float2bfloat16(v.w - __bfloat162float(h3));
    __nv_bfloat162* hp = (__nv_bfloat162*)(hi + 4 * (size_t)i);
    __nv_bfloat162* lp = (__nv_bfloat162*)(lo + 4 * (size_t)i);
    hp[0] = __nv_bfloat162(h0, h1); hp[1] = __nv_bfloat162(h2, h3);
    lp[0] = __nv_bfloat162(l0, l1); lp[1] = __nv_bfloat162(l2, l3);
}

// 4 weight transposes in one launch
__global__ void transpose_split_kernel(const float* __restrict__ W0,
                                       const float* __restrict__ W1,
                                       const float* __restrict__ W2,
                                       const float* __restrict__ W3,
                                       __nv_bfloat16* __restrict__ ThiB,
                                       __nv_bfloat16* __restrict__ TloB) {
    __shared__ float t[32][33];
    const int z = blockIdx.z;
    const float* W = (z == 0) ? W0 : (z == 1) ? W1 : (z == 2) ? W2 : W3;
    __nv_bfloat16* Thi = ThiB + (size_t)z * D_ * D_;
    __nv_bfloat16* Tlo = TloB + (size_t)z * D_ * D_;
    const int n0 = blockIdx.x * 32, k0 = blockIdx.y * 32;
    for (int j = threadIdx.y; j < 32; j += 8)
        t[j][threadIdx.x] = W[(size_t)(k0 + j) * D_ + n0 + threadIdx.x];
    __syncthreads();
    for (int j = threadIdx.y; j < 32; j += 8) {
        float v = t[threadIdx.x][j];
        __nv_bfloat16 h = __float2bfloat16(v);
        __nv_bfloat16 l = __float2bfloat16(v - __bfloat162float(h));
        size_t o = (size_t)(n0 + j) * D_ + k0 + threadIdx.x;
        Thi[o] = h; Tlo[o] = l;
    }
}

// ======================= mma.sync bf16x3 GEMM (R9, measured-equal best) ======
#define KC   64
#define SSTR 72
#define SM_A (128 * SSTR)
#define SM_B (64 * SSTR)
#define GEMM_SMEM ((2 * SM_A + 2 * SM_B) * 2)    // 55296 B

__device__ __forceinline__ void gemm_mainloop(const __nv_bfloat16* __restrict__ Ahi,
                                              const __nv_bfloat16* __restrict__ Alo,
                                              const __nv_bfloat16* __restrict__ Bhi,
                                              const __nv_bfloat16* __restrict__ Blo,
                                              __nv_bfloat16* smb,
                                              int rowBase, int colBase,
                                              float acc[4][4][4]) {
    __nv_bfloat16* As_h = smb;
    __nv_bfloat16* As_l = As_h + SM_A;
    __nv_bfloat16* Bs_h = As_l + SM_A;
    __nv_bfloat16* Bs_l = Bs_h + SM_B;

    const int tid  = threadIdx.x;
    const int lane = tid & 31;
    const int wid  = tid >> 5;
    const int wm   = wid >> 1;
    const int wn   = wid & 1;

    const uint32_t sAh = smem_u32(As_h);
    const uint32_t sAl = smem_u32(As_l);
    const uint32_t sBh = smem_u32(Bs_h);
    const uint32_t sBl = smem_u32(Bs_l);

    const int r0 = tid >> 3;
    const int cs = (tid & 7) * 8;

    const int aRow = ((lane & 8) ? 8 : 0) + (lane & 7);
    const int aK   = ((lane & 16) ? 8 : 0);
    const int bRow = ((lane & 16) ? 8 : 0) + (lane & 7);
    const int bK   = ((lane & 8) ? 8 : 0);

    for (int c = 0; c < 16; c++) {
        const int kb = c * KC;
        if (c) __syncthreads();
        #pragma unroll
        for (int u = 0; u < 8; u++) {
            const int r = u * 16 + r0;
            const size_t ga = (size_t)(rowBase + r) * D_ + kb + cs;
            const int so = r * SSTR + cs;
            *(uint4*)(As_h + so) = *(const uint4*)(Ahi + ga);
            *(uint4*)(As_l + so) = *(const uint4*)(Alo + ga);
        }
        #pragma unroll
        for (int u = 0; u < 4; u++) {
            const int r = u * 16 + r0;
            const size_t gb = (size_t)(colBase + r) * D_ + kb + cs;
            const int so = r * SSTR + cs;
            *(uint4*)(Bs_h + so) = *(const uint4*)(Bhi + gb);
            *(uint4*)(Bs_l + so) = *(const uint4*)(Blo + gb);
        }
        __syncthreads();

        #pragma unroll
        for (int k16 = 0; k16 < 4; k16++) {
            const int kk = k16 * 16;
            uint32_t bh[4][2], bl[4][2];
            #pragma unroll
            for (int g = 0; g < 2; g++) {
                const uint32_t off =
                    (uint32_t)((wn * 32 + g * 16 + bRow) * SSTR + kk + bK) * 2;
                uint32_t t4[4];
                ldsm_x4(t4, sBh + off);
                bh[2*g][0] = t4[0]; bh[2*g][1] = t4[1];
                bh[2*g+1][0] = t4[2]; bh[2*g+1][1] = t4[3];
                ldsm_x4(t4, sBl + off);
                bl[2*g][0] = t4[0]; bl[2*g][1] = t4[1];
                bl[2*g+1][0] = t4[2]; bl[2*g+1][1] = t4[3];
            }
            #pragma unroll
            for (int mi = 0; mi < 4; mi++) {
                const uint32_t offA =
                    (uint32_t)((wm * 64 + mi * 16 + aRow) * SSTR + kk + aK) * 2;
                uint32_t ah[4], al[4];
                ldsm_x4(ah, sAh + offA);
                ldsm_x4(al, sAl + offA);
                #pragma unroll
                for (int ni = 0; ni < 4; ni++) {
                    mma16816(acc[mi][ni], ah, bh[ni]);
                    mma16816(acc[mi][ni], ah, bl[ni]);
                    mma16816(acc[mi][ni], al, bh[ni]);
                }
            }
        }
    }
}

__global__ void __launch_bounds__(128) qkv_gemm() {
    extern __shared__ __nv_bfloat16 smb[];
    const int rowBase = blockIdx.y * 128;
    const int colBase = blockIdx.x * 64;
    const int z = colBase >> 10;
    __nv_bfloat16* Chi = (z == 0) ? g_qh : (z == 1) ? g_kh : g_vh;
    __nv_bfloat16* Clo = (z == 0) ? g_ql : (z == 1) ? g_kl : g_vl;
    const int colLoc = colBase & 1023;

    float acc[4][4][4];
    #pragma unroll
    for (int i = 0; i < 4; i++)
        #pragma unroll
        for (int j = 0; j < 4; j++)
            #pragma unroll
            for (int q = 0; q < 4; q++) acc[i][j][q] = 0.f;

    gemm_mainloop(g_xhi, g_xlo, g_wthi, g_wtlo, smb, rowBase, colBase, acc);

    const int lane = threadIdx.x & 31;
    const int wid  = threadIdx.x >> 5;
    const int wm   = wid >> 1;
    const int wn   = wid & 1;
    const int qr = lane >> 2;
    const int qc = (lane & 3) * 2;
    #pragma unroll
    for (int mi = 0; mi < 4; mi++) {
        const int m0 = rowBase + wm * 64 + mi * 16 + qr;
        #pragma unroll
        for (int ni = 0; ni < 4; ni++) {
            const int cc = colLoc + wn * 32 + ni * 8 + qc;
            #pragma unroll
            for (int rr = 0; rr < 2; rr++) {
                const float f0 = acc[mi][ni][rr*2+0];
                const float f1 = acc[mi][ni][rr*2+1];
                __nv_bfloat16 h0 = __float2bfloat16(f0);
                __nv_bfloat16 h1 = __float2bfloat16(f1);
                __nv_bfloat16 l0 = __float2bfloat16(f0 - __bfloat162float(h0));
                __nv_bfloat16 l1 = __float2bfloat16(f1 - __bfloat162float(h1));
                const size_t o = (size_t)(m0 + rr * 8) * D_ + cc;
                *(__nv_bfloat162*)(Chi + o) = __nv_bfloat162(h0, h1);
                *(__nv_bfloat162*)(Clo + o) = __nv_bfloat162(l0, l1);
            }
        }
    }
}

__global__ void __launch_bounds__(128) out_gemm(const float* __restrict__ bias,
                                                float* __restrict__ C) {
    extern __shared__ __nv_bfloat16 smb[];
    const int rowBase = blockIdx.y * 128;
    const int colBase = blockIdx.x * 64;

    float acc[4][4][4];
    #pragma unroll
    for (int i = 0; i < 4; i++)
        #pragma unroll
        for (int j = 0; j < 4; j++)
            #pragma unroll
            for (int q = 0; q < 4; q++) acc[i][j][q] = 0.f;

    gemm_mainloop(g_chi, g_clo,
                  g_wthi + 3 * (size_t)D_ * D_, g_wtlo + 3 * (size_t)D_ * D_,
                  smb, rowBase, colBase, acc);

    const int lane = threadIdx.x & 31;
    const int wid  = threadIdx.x >> 5;
    const int wm   = wid >> 1;
    const int wn   = wid & 1;
    const int qr = lane >> 2;
    const int qc = (lane & 3) * 2;
    #pragma unroll
    for (int mi = 0; mi < 4; mi++) {
        const int m0 = rowBase + wm * 64 + mi * 16 + qr;
        #pragma unroll
        for (int ni = 0; ni < 4; ni++) {
            const int cc = colBase + wn * 32 + ni * 8 + qc;
            float b0 = bias[cc], b1 = bias[cc + 1];
            float2 v0; v0.x = acc[mi][ni][0] + b0; v0.y = acc[mi][ni][1] + b1;
            float2 v1; v1.x = acc[mi][ni][2] + b0; v1.y = acc[mi][ni][3] + b1;
            *(float2*)&C[(size_t)m0 * D_ + cc] = v0;
            *(float2*)&C[(size_t)(m0 + 8) * D_ + cc] = v1;
        }
    }
}

// ---------------- per-(b,h) V row-sum: 8 partial blocks per bh + atomics -----
__global__ void vsum_kernel() {
    __shared__ float red[256];
    const int bh = blockIdx.x;
    const int part = blockIdx.y;
    const int b  = bh / H_, h = bh % H_;
    const int dk = threadIdx.x & 63;
    const int grp = threadIdx.x >> 6;
    const __nv_bfloat16* Vh = g_vh + (size_t)b * S_ * D_ + h * DK_ + dk;
    const __nv_bfloat16* Vl = g_vl + (size_t)b * S_ * D_ + h * DK_ + dk;
    float s = 0.f;
    const int base = part * 256 + grp * 64;
    for (int i = 0; i < 64; i++) {
        const size_t r = (size_t)(base + i) * D_;
        s += __bfloat162float(Vh[r]) + __bfloat162float(Vl[r]);
    }
    red[threadIdx.x] = s;
    __syncthreads();
    if (threadIdx.x < 64) {
        float t = red[threadIdx.x] + red[threadIdx.x + 64]
                + red[threadIdx.x + 128] + red[threadIdx.x + 192];
        atomicAdd(&g_vsum[bh * DK_ + threadIdx.x], t);
    }
}

// ================= flash attention: 128 q-rows/CTA, 256 threads ==============
// Q resident (128x64 hi/lo), K/V tiles 64 keys. Per-warp inner code identical
// to the proven 64-row kernel; K/V staging per MMA halved.
#define FS 72
#define FLASH_SMEM ((2 * 128 * FS + 4 * 64 * FS) * 2 + 64 * 4)   // 73984 B

__global__ void __launch_bounds__(256) flash_mma(const int* __restrict__ kpm) {
    extern __shared__ __nv_bfloat16 fsm[];
    __nv_bfloat16* Qh = fsm;                   // 128 x FS
    __nv_bfloat16* Ql = Qh + 128 * FS;
    __nv_bfloat16* Kh = Ql + 128 * FS;         // 64 x FS
    __nv_bfloat16* Kl = Kh + 64 * FS;
    __nv_bfloat16* Vh = Kl + 64 * FS;
    __nv_bfloat16* Vl = Vh + 64 * FS;
    int* pads = (int*)(Vl + 64 * FS);

    const int tid  = threadIdx.x;
    const int lane = tid & 31;
    const int wq   = tid >> 5;                 // 0..7
    const int qblk = (int)gridDim.x - 1 - (int)blockIdx.x;   // big tiles first
    const int bh   = blockIdx.y;
    const int b = bh / H_, h = bh % H_;

    const uint32_t sQh = smem_u32(Qh), sQl = smem_u32(Ql);
    const uint32_t sKh = smem_u32(Kh), sKl = smem_u32(Kl);
    const uint32_t sVh = smem_u32(Vh), sVl = smem_u32(Vl);

    const size_t headOff = (size_t)b * S_ * D_ + h * DK_;
    const size_t qOff = headOff + (size_t)(qblk * 128) * D_;

    // load Q tile (128 rows x 64 cols, hi/lo)
    #pragma unroll
    for (int u = 0; u < 4; u++) {
        const int idx = u * 256 + tid;
        const int r = idx >> 3, c = (idx & 7) * 8;
        *(uint4*)(Qh + r * FS + c) = *(const uint4*)(g_qh + qOff + (size_t)r * D_ + c);
        *(uint4*)(Ql + r * FS + c) = *(const uint4*)(g_ql + qOff + (size_t)r * D_ + c);
    }

    const int aRow = ((lane & 8) ? 8 : 0) + (lane & 7);
    const int aK   = ((lane & 16) ? 8 : 0);
    const int bRow = ((lane & 16) ? 8 : 0) + (lane & 7);
    const int bK   = ((lane & 8) ? 8 : 0);
    const int vRow = ((lane & 8) ? 8 : 0) + (lane & 7);
    const int vCol = ((lane & 16) ? 8 : 0);

    float m0 = -INFINITY, m1 = -INFINITY, l0 = 0.f, l1 = 0.f;
    float oacc[8][4];
    #pragma unroll
    for (int ni = 0; ni < 8; ni++)
        #pragma unroll
        for (int q = 0; q < 4; q++) oacc[ni][q] = 0.f;

    const int qr0 = qblk * 128 + wq * 16 + (lane >> 2);
    const int qr1 = qr0 + 8;
    const int colq = (lane & 3) * 2;

    const int nkt = 2 * qblk + 2;              // k-tiles 0 .. 2*qblk+1
    for (int kt = 0; kt < nkt; kt++) {
        __syncthreads();
        {
            const size_t kOff = headOff + (size_t)(kt * 64) * D_;
            #pragma unroll
            for (int u = 0; u < 2; u++) {
                const int idx = u * 256 + tid;
                const int r = idx >> 3, c = (idx & 7) * 8;
                const size_t go = kOff + (size_t)r * D_ + c;
                const int so = r * FS + c;
                *(uint4*)(Kh + so) = *(const uint4*)(g_kh + go);
                *(uint4*)(Kl + so) = *(const uint4*)(g_kl + go);
                *(uint4*)(Vh + so) = *(const uint4*)(g_vh + go);
                *(uint4*)(Vl + so) = *(const uint4*)(g_vl + go);
            }
            if (tid < 64) pads[tid] = kpm[b * S_ + kt * 64 + tid];
        }
        __syncthreads();

        float sacc[8][4];
        #pragma unroll
        for (int ni = 0; ni < 8; ni++)
            #pragma unroll
            for (int q = 0; q < 4; q++) sacc[ni][q] = 0.f;

        #pragma unroll
        for (int j = 0; j < 4; j++) {
            const int kk = j * 16;
            uint32_t ah[4], al[4];
            ldsm_x4(ah, sQh + (uint32_t)((wq * 16 + aRow) * FS + kk + aK) * 2);
            ldsm_x4(al, sQl + (uint32_t)((wq * 16 + aRow) * FS + kk + aK) * 2);
            #pragma unroll
            for (int g = 0; g < 4; g++) {
                const uint32_t off = (uint32_t)((g * 16 + bRow) * FS + kk + bK) * 2;
                uint32_t th[4], tl[4];
                ldsm_x4(th, sKh + off);
                ldsm_x4(tl, sKl + off);
                mma16816(sacc[2*g],   ah, th);
                mma16816(sacc[2*g],   ah, tl);
                mma16816(sacc[2*g],   al, th);
                mma16816(sacc[2*g+1], ah, th + 2);
                mma16816(sacc[2*g+1], ah, tl + 2);
                mma16816(sacc[2*g+1], al, th + 2);
            }
        }

        const bool diag = (kt >= 2 * qblk);    // only last two tiles need masking
        #pragma unroll
        for (int ni = 0; ni < 8; ni++) {
            const int kc = kt * 64 + ni * 8 + colq;
            const int p0 = pads[ni * 8 + colq];
            const int p1 = pads[ni * 8 + colq + 1];
            bool v00 = !p0, v01 = !p1, v10 = !p0, v11 = !p1;
            if (diag) {
                v00 = v00 && (kc     <= qr0);
                v01 = v01 && (kc + 1 <= qr0);
                v10 = v10 && (kc     <= qr1);
                v11 = v11 && (kc + 1 <= qr1);
            }
            sacc[ni][0] = v00 ? sacc[ni][0] * 0.125f : -INFINITY;
            sacc[ni][1] = v01 ? sacc[ni][1] * 0.125f : -INFINITY;
            sacc[ni][2] = v10 ? sacc[ni][2] * 0.125f : -INFINITY;
            sacc[ni][3] = v11 ? sacc[ni][3] * 0.125f : -INFINITY;
        }

        float mt0 = -INFINITY, mt1 = -INFINITY;
        #pragma unroll
        for (int ni = 0; ni < 8; ni++) {
            mt0 = fmaxf(mt0, fmaxf(sacc[ni][0], sacc[ni][1]));
            mt1 = fmaxf(mt1, fmaxf(sacc[ni][2], sacc[ni][3]));
        }
        mt0 = fmaxf(mt0, __shfl_xor_sync(0xffffffffu, mt0, 1));
        mt0 = fmaxf(mt0, __shfl_xor_sync(0xffffffffu, mt0, 2));
        mt1 = fmaxf(mt1, __shfl_xor_sync(0xffffffffu, mt1, 1));
        mt1 = fmaxf(mt1, __shfl_xor_sync(0xffffffffu, mt1, 2));

        const float mn0 = fmaxf(m0, mt0);
        const float mn1 = fmaxf(m1, mt1);
        const bool live0 = (mn0 != -INFINITY);
        const bool live1 = (mn1 != -INFINITY);
        const float alpha0 = live0 ? __expf(m0 - mn0) : 1.f;
        const float alpha1 = live1 ? __expf(m1 - mn1) : 1.f;

        float ps0 = 0.f, ps1 = 0.f;
        #pragma unroll
        for (int ni = 0; ni < 8; ni++) {
            float p00 = live0 ? __expf(sacc[ni][0] - mn0) : 0.f;
            float p01 = live0 ? __expf(sacc[ni][1] - mn0) : 0.f;
            float p10 = live1 ? __expf(sacc[ni][2] - mn1) : 0.f;
            float p11 = live1 ? __expf(sacc[ni][3] - mn1) : 0.f;
            sacc[ni][0] = p00; sacc[ni][1] = p01;
            sacc[ni][2] = p10; sacc[ni][3] = p11;
            ps0 += p00 + p01;
            ps1 += p10 + p11;
        }
        ps0 += __shfl_xor_sync(0xffffffffu, ps0, 1);
        ps0 += __shfl_xor_sync(0xffffffffu, ps0, 2);
        ps1 += __shfl_xor_sync(0xffffffffu, ps1, 1);
        ps1 += __shfl_xor_sync(0xffffffffu, ps1, 2);

        l0 = l0 * alpha0 + ps0;
        l1 = l1 * alpha1 + ps1;
        m0 = mn0; m1 = mn1;
        #pragma unroll
        for (int ni = 0; ni < 8; ni++) {
            oacc[ni][0] *= alpha0; oacc[ni][1] *= alpha0;
            oacc[ni][2] *= alpha1; oacc[ni][3] *= alpha1;
        }

        #pragma unroll
        for (int j = 0; j < 4; j++) {
            uint32_t af_h[4], af_l[4];
            #pragma unroll
            for (int t = 0; t < 2; t++) {
                const float f0 = sacc[2*j+t][0], f1 = sacc[2*j+t][1];
                const float f2 = sacc[2*j+t][2], f3 = sacc[2*j+t][3];
                const uint32_t h01 = pack_bf16x2(f0, f1);
                const uint32_t h23 = pack_bf16x2(f2, f3);
                __nv_bfloat162 hb01 = *(__nv_bfloat162*)&h01;
                __nv_bfloat162 hb23 = *(__nv_bfloat162*)&h23;
                af_h[2*t]   = h01;
                af_h[2*t+1] = h23;
                af_l[2*t]   = pack_bf16x2(f0 - __bfloat162float(hb01.x),
                                          f1 - __bfloat162float(hb01.y));
                af_l[2*t+1] = pack_bf16x2(f2 - __bfloat162float(hb23.x),
                                          f3 - __bfloat162float(hb23.y));
            }
            #pragma unroll
            for (int g = 0; g < 4; g++) {
                const uint32_t off =
                    (uint32_t)((j * 16 + vRow) * FS + g * 16 + vCol) * 2;
                uint32_t vbh[4], vbl[4];
                ldsm_x4_t(vbh, sVh + off);
                ldsm_x4_t(vbl, sVl + off);
                mma16816(oacc[2*g],   af_h, vbh);
                mma16816(oacc[2*g],   af_h, vbl);
                mma16816(oacc[2*g],   af_l, vbh);
                mma16816(oacc[2*g+1], af_h, vbh + 2);
                mma16816(oacc[2*g+1], af_h, vbl + 2);
                mma16816(oacc[2*g+1], af_l, vbh + 2);
            }
        }
    }

    const float invS = 1.0f / (float)S_;
    const bool dead0 = (m0 == -INFINITY);
    const bool dead1 = (m1 == -INFINITY);
    const float inv0 = dead0 ? 0.f : 1.0f / l0;
    const float inv1 = dead1 ? 0.f : 1.0f / l1;
    const size_t row0 = (size_t)b * S_ + qr0;
    const size_t row1 = (size_t)b * S_ + qr1;
    #pragma unroll
    for (int ni = 0; ni < 8; ni++) {
        const int dd = ni * 8 + colq;
        float v00, v01, v10, v11;
        if (dead0) {
            v00 = g_vsum[bh * DK_ + dd] * invS;
            v01 = g_vsum[bh * DK_ + dd + 1] * invS;
        } else { v00 = oacc[ni][0] * inv0; v01 = oacc[ni][1] * inv0; }
        if (dead1) {
            v10 = g_vsum[bh * DK_ + dd] * invS;
            v11 = g_vsum[bh * DK_ + dd + 1] * invS;
        } else { v10 = oacc[ni][2] * inv1; v11 = oacc[ni][3] * inv1; }

        __nv_bfloat16 h00 = __float2bfloat16(v00), h01 = __float2bfloat16(v01);
        __nv_bfloat16 h10 = __float2bfloat16(v10), h11 = __float2bfloat16(v11);
        const size_t o0 = row0 * D_ + h * DK_ + dd;
        const size_t o1 = row1 * D_ + h * DK_ + dd;
        *(__nv_bfloat162*)(g_chi + o0) = __nv_bfloat162(h00, h01);
        *(__nv_bfloat162*)(g_chi + o1) = __nv_bfloat162(h10, h11);
        *(__nv_bfloat162*)(g_clo + o0) =
            __nv_bfloat162(__float2bfloat16(v00 - __bfloat162float(h00)),
                           __float2bfloat16(v01 - __bfloat162float(h01)));
        *(__nv_bfloat162*)(g_clo + o1) =
            __nv_bfloat162(__float2bfloat16(v10 - __bfloat162float(h10)),
                           __float2bfloat16(v11 - __bfloat162float(h11)));
    }
}

// ---------------- launch ------------------------------------------------------
extern "C" void kernel_launch(void* const* d_in, const int* in_sizes, int n_in,
                              void* d_out, int out_size) {
    const float* x   = (const float*)d_in[0];
    const int*   kpm = (const int*)d_in[2];
    const float* Wq  = (const float*)d_in[3];
    const float* Wk  = (const float*)d_in[4];
    const float* Wv  = (const float*)d_in[5];
    const float* Wo  = (const float*)d_in[6];
    const float* bo  = (const float*)d_in[7];
    float* out = (float*)d_out;

    __nv_bfloat16 *xhi, *xlo, *wthi, *wtlo;
    float* vsum;
    cudaGetSymbolAddress((void**)&xhi, g_xhi);
    cudaGetSymbolAddress((void**)&xlo, g_xlo);
    cudaGetSymbolAddress((void**)&wthi, g_wthi);
    cudaGetSymbolAddress((void**)&wtlo, g_wtlo);
    cudaGetSymbolAddress((void**)&vsum, g_vsum);

    cudaFuncSetAttribute(qkv_gemm, cudaFuncAttributeMaxDynamicSharedMemorySize, GEMM_SMEM);
    cudaFuncSetAttribute(out_gemm, cudaFuncAttributeMaxDynamicSharedMemorySize, GEMM_SMEM);
    cudaFuncSetAttribute(flash_mma, cudaFuncAttributeMaxDynamicSharedMemorySize, FLASH_SMEM);

    // 0) zero vsum (capture-safe async memset)
    cudaMemsetAsync(vsum, 0, B_ * H_ * DK_ * sizeof(float));

    // 1) split x
    split_kernel<<<(MROWS * D_ / 4) / 256, 256>>>(x, xhi, xlo);

    // 2) transpose+split all four weights in one launch
    dim3 tb(32, 8), tg(32, 32, 4);
    transpose_split_kernel<<<tg, tb>>>(Wq, Wk, Wv, Wo, wthi, wtlo);

    // 3) fused Q/K/V projections
    dim3 gq(3 * D_ / 64, MROWS / 128);   // (48, 32)
    qkv_gemm<<<gq, 128, GEMM_SMEM>>>();

    // 4) V row-sums (parallel, atomics)
    dim3 gv(B_ * H_, 8);
    vsum_kernel<<<gv, 256>>>();

    // 5) flash attention: 128 q-rows per CTA
    dim3 fg(S_ / 128, B_ * H_);          // (16, 32)
    flash_mma<<<fg, 256, FLASH_SMEM>>>(kpm);

    // 6) output projection with bias (fp32 out)
    dim3 gg(D_ / 64, MROWS / 128);       // (16, 32)
    out_gemm<<<gg, 128, GEMM_SMEM>>>(bo, out);
}

// round 11
// speedup vs baseline: 1.3906x; 1.3906x over previous
#include <cuda_runtime.h>
#include <cuda_fp16.h>
#include <math.h>
#include <stdint.h>

#define B_  2
#define S_  2048
#define D_  1024
#define H_  16
#define DK_ 64
#define MROWS (B_*S_)      // 4096

// ---------------- scratch (allocation-free: __device__ globals) -------------
__device__ __half g_qh[MROWS*D_];          // Q: A-operand, single fp16
__device__ __half g_kh[MROWS*D_];          // K: B-operand, hi
__device__ __half g_kl[MROWS*D_];          //    lo
__device__ __half g_vh[MROWS*D_];          // V: B-operand, hi
__device__ __half g_vl[MROWS*D_];          //    lo
__device__ __half g_ch[MROWS*D_];          // ctx: A-operand, single fp16
__device__ __half g_xh[MROWS*D_];          // x: A-operand, single fp16
__device__ __half g_wh[4*D_*D_];           // W^T [N,K] hi (4 matrices contiguous)
__device__ __half g_wl[4*D_*D_];           //             lo
__device__ float g_vsum[B_*H_*DK_];

// ======================= helpers =============================================
__device__ __forceinline__ uint32_t smem_u32(const void* p) {
    uint32_t a;
    asm("{ .reg .u64 t; cvta.to.shared.u64 t, %1; cvt.u32.u64 %0, t; }"
        : "=r"(a) : "l"(p));
    return a;
}
__device__ __forceinline__ void ldsm_x4(uint32_t* r, uint32_t addr) {
    asm volatile("ldmatrix.sync.aligned.m8n8.x4.shared.b16 {%0,%1,%2,%3}, [%4];"
                 : "=r"(r[0]), "=r"(r[1]), "=r"(r[2]), "=r"(r[3]) : "r"(addr));
}
__device__ __forceinline__ void ldsm_x4_t(uint32_t* r, uint32_t addr) {
    asm volatile("ldmatrix.sync.aligned.m8n8.x4.trans.shared.b16 {%0,%1,%2,%3}, [%4];"
                 : "=r"(r[0]), "=r"(r[1]), "=r"(r[2]), "=r"(r[3]) : "r"(addr));
}
__device__ __forceinline__ void mma16816(float* c, const uint32_t* a, const uint32_t* b) {
    asm volatile("mma.sync.aligned.m16n8k16.row.col.f32.f16.f16.f32 "
                 "{%0,%1,%2,%3}, {%4,%5,%6,%7}, {%8,%9}, {%0,%1,%2,%3};"
                 : "+f"(c[0]), "+f"(c[1]), "+f"(c[2]), "+f"(c[3])
                 : "r"(a[0]), "r"(a[1]), "r"(a[2]), "r"(a[3]),
                   "r"(b[0]), "r"(b[1]));
}
__device__ __forceinline__ uint32_t pack_h2(float a, float b) {
    __half2 t = __floats2half2_rn(a, b);
    return *(uint32_t*)&t;
}

// ======================= preprocessing kernels ==============================
// x fp32 -> fp16 (single)
__global__ void convert_kernel(const float* __restrict__ src,
                               __half* __restrict__ dst) {
    int i = blockIdx.x * blockDim.x + threadIdx.x;
    float4 v = ((const float4*)src)[i];
    __half2* dp = (__half2*)(dst + 4 * (size_t)i);
    dp[0] = __floats2half2_rn(v.x, v.y);
    dp[1] = __floats2half2_rn(v.z, v.w);
}

// 4 weight transposes in one launch: W[K,N] f32 -> WT[N,K] fp16 hi + lo
__global__ void transpose_split_kernel(const float* __restrict__ W0,
                                       const float* __restrict__ W1,
                                       const float* __restrict__ W2,
                                       const float* __restrict__ W3,
                                       __half* __restrict__ ThiB,
                                       __half* __restrict__ TloB) {
    __shared__ float t[32][33];
    const int z = blockIdx.z;
    const float* W = (z == 0) ? W0 : (z == 1) ? W1 : (z == 2) ? W2 : W3;
    __half* Thi = ThiB + (size_t)z * D_ * D_;
    __half* Tlo = TloB + (size_t)z * D_ * D_;
    const int n0 = blockIdx.x * 32, k0 = blockIdx.y * 32;
    for (int j = threadIdx.y; j < 32; j += 8)
        t[j][threadIdx.x] = W[(size_t)(k0 + j) * D_ + n0 + threadIdx.x];
    __syncthreads();
    for (int j = threadIdx.y; j < 32; j += 8) {
        float v = t[threadIdx.x][j];
        __half h = __float2half(v);
        __half l = __float2half(v - __half2float(h));
        size_t o = (size_t)(n0 + j) * D_ + k0 + threadIdx.x;
        Thi[o] = h; Tlo[o] = l;
    }
}

// ======================= fp16 2-term GEMM ====================================
// C = A(fp16) @ (Bh + Bl)^T, fp32 accumulate. 128 threads, tile 128(M)x64(N),
// warps 2m x 2n, warp tile 64x32. KC=64 single buffer, LDG->STS staging.
#define KC   64
#define SSTR 72
#define SM_A (128 * SSTR)
#define SM_B (64 * SSTR)
#define GEMM_SMEM ((SM_A + 2 * SM_B) * 2)    // 36864 B

__device__ __forceinline__ void gemm_mainloop(const __half* __restrict__ A,
                                              const __half* __restrict__ Bhp,
                                              const __half* __restrict__ Blp,
                                              __half* smb,
                                              int rowBase, int colBase,
                                              float acc[4][4][4]) {
    __half* As   = smb;
    __half* Bs_h = As + SM_A;
    __half* Bs_l = Bs_h + SM_B;

    const int tid  = threadIdx.x;
    const int lane = tid & 31;
    const int wid  = tid >> 5;
    const int wm   = wid >> 1;
    const int wn   = wid & 1;

    const uint32_t sA  = smem_u32(As);
    const uint32_t sBh = smem_u32(Bs_h);
    const uint32_t sBl = smem_u32(Bs_l);

    const int r0 = tid >> 3;
    const int cs = (tid & 7) * 8;

    const int aRow = ((lane & 8) ? 8 : 0) + (lane & 7);
    const int aK   = ((lane & 16) ? 8 : 0);
    const int bRow = ((lane & 16) ? 8 : 0) + (lane & 7);
    const int bK   = ((lane & 8) ? 8 : 0);

    for (int c = 0; c < 16; c++) {
        const int kb = c * KC;
        if (c) __syncthreads();
        #pragma unroll
        for (int u = 0; u < 8; u++) {
            const int r = u * 16 + r0;
            const size_t ga = (size_t)(rowBase + r) * D_ + kb + cs;
            *(uint4*)(As + r * SSTR + cs) = *(const uint4*)(A + ga);
        }
        #pragma unroll
        for (int u = 0; u < 4; u++) {
            const int r = u * 16 + r0;
            const size_t gb = (size_t)(colBase + r) * D_ + kb + cs;
            const int so = r * SSTR + cs;
            *(uint4*)(Bs_h + so) = *(const uint4*)(Bhp + gb);
            *(uint4*)(Bs_l + so) = *(const uint4*)(Blp + gb);
        }
        __syncthreads();

        #pragma unroll
        for (int k16 = 0; k16 < 4; k16++) {
            const int kk = k16 * 16;
            uint32_t bh[4][2], bl[4][2];
            #pragma unroll
            for (int g = 0; g < 2; g++) {
                const uint32_t off =
                    (uint32_t)((wn * 32 + g * 16 + bRow) * SSTR + kk + bK) * 2;
                uint32_t t4[4];
                ldsm_x4(t4, sBh + off);
                bh[2*g][0] = t4[0]; bh[2*g][1] = t4[1];
                bh[2*g+1][0] = t4[2]; bh[2*g+1][1] = t4[3];
                ldsm_x4(t4, sBl + off);
                bl[2*g][0] = t4[0]; bl[2*g][1] = t4[1];
                bl[2*g+1][0] = t4[2]; bl[2*g+1][1] = t4[3];
            }
            #pragma unroll
            for (int mi = 0; mi < 4; mi++) {
                const uint32_t offA =
                    (uint32_t)((wm * 64 + mi * 16 + aRow) * SSTR + kk + aK) * 2;
                uint32_t ah[4];
                ldsm_x4(ah, sA + offA);
                #pragma unroll
                for (int ni = 0; ni < 4; ni++) {
                    mma16816(acc[mi][ni], ah, bh[ni]);
                    mma16816(acc[mi][ni], ah, bl[ni]);
                }
            }
        }
    }
}

// fused QKV: single GEMM vs [3072,1024] weight block; z = colBase>>10
__global__ void __launch_bounds__(128) qkv_gemm() {
    extern __shared__ __half smb[];
    const int rowBase = blockIdx.y * 128;
    const int colBase = blockIdx.x * 64;       // [0, 3072)
    const int z = colBase >> 10;               // 0=Q 1=K 2=V
    const int colLoc = colBase & 1023;

    float acc[4][4][4];
    #pragma unroll
    for (int i = 0; i < 4; i++)
        #pragma unroll
        for (int j = 0; j < 4; j++)
            #pragma unroll
            for (int q = 0; q < 4; q++) acc[i][j][q] = 0.f;

    gemm_mainloop(g_xh, g_wh, g_wl, smb, rowBase, colBase, acc);

    const int lane = threadIdx.x & 31;
    const int wid  = threadIdx.x >> 5;
    const int wm   = wid >> 1;
    const int wn   = wid & 1;
    const int qr = lane >> 2;
    const int qc = (lane & 3) * 2;

    __half* Chi = (z == 0) ? g_qh : (z == 1) ? g_kh : g_vh;
    __half* Clo = (z == 1) ? g_kl : g_vl;      // unused for z==0

    #pragma unroll
    for (int mi = 0; mi < 4; mi++) {
        const int m0 = rowBase + wm * 64 + mi * 16 + qr;
        #pragma unroll
        for (int ni = 0; ni < 4; ni++) {
            const int cc = colLoc + wn * 32 + ni * 8 + qc;
            #pragma unroll
            for (int rr = 0; rr < 2; rr++) {
                const float f0 = acc[mi][ni][rr*2+0];
                const float f1 = acc[mi][ni][rr*2+1];
                __half h0 = __float2half(f0);
                __half h1 = __float2half(f1);
                const size_t o = (size_t)(m0 + rr * 8) * D_ + cc;
                *(__half2*)(Chi + o) = __half2(h0, h1);
                if (z != 0) {
                    __half l0 = __float2half(f0 - __half2float(h0));
                    __half l1 = __float2half(f1 - __half2float(h1));
                    *(__half2*)(Clo + o) = __half2(l0, l1);
                }
            }
        }
    }
}

// output projection with bias, fp32 out
__global__ void __launch_bounds__(128) out_gemm(const float* __restrict__ bias,
                                                float* __restrict__ C) {
    extern __shared__ __half smb[];
    const int rowBase = blockIdx.y * 128;
    const int colBase = blockIdx.x * 64;

    float acc[4][4][4];
    #pragma unroll
    for (int i = 0; i < 4; i++)
        #pragma unroll
        for (int j = 0; j < 4; j++)
            #pragma unroll
            for (int q = 0; q < 4; q++) acc[i][j][q] = 0.f;

    gemm_mainloop(g_ch,
                  g_wh + 3 * (size_t)D_ * D_, g_wl + 3 * (size_t)D_ * D_,
                  smb, rowBase, colBase, acc);

    const int lane = threadIdx.x & 31;
    const int wid  = threadIdx.x >> 5;
    const int wm   = wid >> 1;
    const int wn   = wid & 1;
    const int qr = lane >> 2;
    const int qc = (lane & 3) * 2;
    #pragma unroll
    for (int mi = 0; mi < 4; mi++) {
        const int m0 = rowBase + wm * 64 + mi * 16 + qr;
        #pragma unroll
        for (int ni = 0; ni < 4; ni++) {
            const int cc = colBase + wn * 32 + ni * 8 + qc;
            float b0 = bias[cc], b1 = bias[cc + 1];
            float2 v0; v0.x = acc[mi][ni][0] + b0; v0.y = acc[mi][ni][1] + b1;
            float2 v1; v1.x = acc[mi][ni][2] + b0; v1.y = acc[mi][ni][3] + b1;
            *(float2*)&C[(size_t)m0 * D_ + cc] = v0;
            *(float2*)&C[(size_t)(m0 + 8) * D_ + cc] = v1;
        }
    }
}

// ---------------- per-(b,h) V row-sum: 8 partial blocks per bh + atomics -----
__global__ void vsum_kernel() {
    __shared__ float red[256];
    const int bh = blockIdx.x;
    const int part = blockIdx.y;
    const int b  = bh / H_, h = bh % H_;
    const int dk = threadIdx.x & 63;
    const int grp = threadIdx.x >> 6;
    const __half* Vh = g_vh + (size_t)b * S_ * D_ + h * DK_ + dk;
    const __half* Vl = g_vl + (size_t)b * S_ * D_ + h * DK_ + dk;
    float s = 0.f;
    const int base = part * 256 + grp * 64;
    for (int i = 0; i < 64; i++) {
        const size_t r = (size_t)(base + i) * D_;
        s += __half2float(Vh[r]) + __half2float(Vl[r]);
    }
    red[threadIdx.x] = s;
    __syncthreads();
    if (threadIdx.x < 64) {
        float t = red[threadIdx.x] + red[threadIdx.x + 64]
                + red[threadIdx.x + 128] + red[threadIdx.x + 192];
        atomicAdd(&g_vsum[bh * DK_ + threadIdx.x], t);
    }
}

// ================= flash attention (fp16 2-term, 64 q-rows, R4 structure) ====
#define FS 72
#define FLASH_SMEM (5 * 64 * FS * 2 + 64 * 4)    // 46336 B

__global__ void __launch_bounds__(128) flash_mma(const int* __restrict__ kpm) {
    extern __shared__ __half fsm[];
    __half* Qs = fsm;                    // 64 x FS (single)
    __half* Kh = Qs + 64 * FS;
    __half* Kl = Kh + 64 * FS;
    __half* Vh = Kl + 64 * FS;
    __half* Vl = Vh + 64 * FS;
    int* pads = (int*)(Vl + 64 * FS);

    const int tid  = threadIdx.x;
    const int lane = tid & 31;
    const int wq   = tid >> 5;
    const int qblk = (int)gridDim.x - 1 - (int)blockIdx.x;   // big tiles first
    const int bh   = blockIdx.y;
    const int b = bh / H_, h = bh % H_;

    const uint32_t sQ  = smem_u32(Qs);
    const uint32_t sKh = smem_u32(Kh), sKl = smem_u32(Kl);
    const uint32_t sVh = smem_u32(Vh), sVl = smem_u32(Vl);

    const size_t headOff = (size_t)b * S_ * D_ + h * DK_;
    const size_t qOff = headOff + (size_t)(qblk * 64) * D_;

    // load Q tile (64 x 64 fp16)
    #pragma unroll
    for (int u = 0; u < 2; u++) {
        const int idx = u * 128 + tid;
        const int r = idx >> 2, c = (idx & 3) * 16;
        *(uint4*)(Qs + r * FS + c)     = *(const uint4*)(g_qh + qOff + (size_t)r * D_ + c);
        *(uint4*)(Qs + r * FS + c + 8) = *(const uint4*)(g_qh + qOff + (size_t)r * D_ + c + 8);
    }

    const int aRow = ((lane & 8) ? 8 : 0) + (lane & 7);
    const int aK   = ((lane & 16) ? 8 : 0);
    const int bRow = ((lane & 16) ? 8 : 0) + (lane & 7);
    const int bK   = ((lane & 8) ? 8 : 0);
    const int vRow = ((lane & 8) ? 8 : 0) + (lane & 7);
    const int vCol = ((lane & 16) ? 8 : 0);

    float m0 = -INFINITY, m1 = -INFINITY, l0 = 0.f, l1 = 0.f;
    float oacc[8][4];
    #pragma unroll
    for (int ni = 0; ni < 8; ni++)
        #pragma unroll
        for (int q = 0; q < 4; q++) oacc[ni][q] = 0.f;

    const int qr0 = qblk * 64 + wq * 16 + (lane >> 2);
    const int qr1 = qr0 + 8;
    const int colq = (lane & 3) * 2;

    for (int kt = 0; kt <= qblk; kt++) {
        __syncthreads();
        {
            const size_t kOff = headOff + (size_t)(kt * 64) * D_;
            #pragma unroll
            for (int u = 0; u < 4; u++) {
                const int idx = u * 128 + tid;
                const int r = idx >> 3, c = (idx & 7) * 8;
                const size_t go = kOff + (size_t)r * D_ + c;
                const int so = r * FS + c;
                *(uint4*)(Kh + so) = *(const uint4*)(g_kh + go);
                *(uint4*)(Kl + so) = *(const uint4*)(g_kl + go);
                *(uint4*)(Vh + so) = *(const uint4*)(g_vh + go);
                *(uint4*)(Vl + so) = *(const uint4*)(g_vl + go);
            }
            if (tid < 64) pads[tid] = kpm[b * S_ + kt * 64 + tid];
        }
        __syncthreads();

        // ---- S = Q @ K^T (fp16 2-term) ----
        float sacc[8][4];
        #pragma unroll
        for (int ni = 0; ni < 8; ni++)
            #pragma unroll
            for (int q = 0; q < 4; q++) sacc[ni][q] = 0.f;

        #pragma unroll
        for (int j = 0; j < 4; j++) {
            const int kk = j * 16;
            uint32_t ah[4];
            ldsm_x4(ah, sQ + (uint32_t)((wq * 16 + aRow) * FS + kk + aK) * 2);
            #pragma unroll
            for (int g = 0; g < 4; g++) {
                const uint32_t off = (uint32_t)((g * 16 + bRow) * FS + kk + bK) * 2;
                uint32_t th[4], tl[4];
                ldsm_x4(th, sKh + off);
                ldsm_x4(tl, sKl + off);
                mma16816(sacc[2*g],   ah, th);
                mma16816(sacc[2*g],   ah, tl);
                mma16816(sacc[2*g+1], ah, th + 2);
                mma16816(sacc[2*g+1], ah, tl + 2);
            }
        }

        // ---- mask + scale ----
        const bool diag = (kt == qblk);
        #pragma unroll
        for (int ni = 0; ni < 8; ni++) {
            const int kc = kt * 64 + ni * 8 + colq;
            const int p0 = pads[ni * 8 + colq];
            const int p1 = pads[ni * 8 + colq + 1];
            bool v00 = !p0, v01 = !p1, v10 = !p0, v11 = !p1;
            if (diag) {
                v00 = v00 && (kc     <= qr0);
                v01 = v01 && (kc + 1 <= qr0);
                v10 = v10 && (kc     <= qr1);
                v11 = v11 && (kc + 1 <= qr1);
            }
            sacc[ni][0] = v00 ? sacc[ni][0] * 0.125f : -INFINITY;
            sacc[ni][1] = v01 ? sacc[ni][1] * 0.125f : -INFINITY;
            sacc[ni][2] = v10 ? sacc[ni][2] * 0.125f : -INFINITY;
            sacc[ni][3] = v11 ? sacc[ni][3] * 0.125f : -INFINITY;
        }

        // ---- online softmax ----
        float mt0 = -INFINITY, mt1 = -INFINITY;
        #pragma unroll
        for (int ni = 0; ni < 8; ni++) {
            mt0 = fmaxf(mt0, fmaxf(sacc[ni][0], sacc[ni][1]));
            mt1 = fmaxf(mt1, fmaxf(sacc[ni][2], sacc[ni][3]));
        }
        mt0 = fmaxf(mt0, __shfl_xor_sync(0xffffffffu, mt0, 1));
        mt0 = fmaxf(mt0, __shfl_xor_sync(0xffffffffu, mt0, 2));
        mt1 = fmaxf(mt1, __shfl_xor_sync(0xffffffffu, mt1, 1));
        mt1 = fmaxf(mt1, __shfl_xor_sync(0xffffffffu, mt1, 2));

        const float mn0 = fmaxf(m0, mt0);
        const float mn1 = fmaxf(m1, mt1);
        const bool live0 = (mn0 != -INFINITY);
        const bool live1 = (mn1 != -INFINITY);
        const float alpha0 = live0 ? __expf(m0 - mn0) : 1.f;
        const float alpha1 = live1 ? __expf(m1 - mn1) : 1.f;

        float ps0 = 0.f, ps1 = 0.f;
        #pragma unroll
        for (int ni = 0; ni < 8; ni++) {
            float p00 = live0 ? __expf(sacc[ni][0] - mn0) : 0.f;
            float p01 = live0 ? __expf(sacc[ni][1] - mn0) : 0.f;
            float p10 = live1 ? __expf(sacc[ni][2] - mn1) : 0.f;
            float p11 = live1 ? __expf(sacc[ni][3] - mn1) : 0.f;
            sacc[ni][0] = p00; sacc[ni][1] = p01;
            sacc[ni][2] = p10; sacc[ni][3] = p11;
            ps0 += p00 + p01;
            ps1 += p10 + p11;
        }
        ps0 += __shfl_xor_sync(0xffffffffu, ps0, 1);
        ps0 += __shfl_xor_sync(0xffffffffu, ps0, 2);
        ps1 += __shfl_xor_sync(0xffffffffu, ps1, 1);
        ps1 += __shfl_xor_sync(0xffffffffu, ps1, 2);

        l0 = l0 * alpha0 + ps0;
        l1 = l1 * alpha1 + ps1;
        m0 = mn0; m1 = mn1;
        #pragma unroll
        for (int ni = 0; ni < 8; ni++) {
            oacc[ni][0] *= alpha0; oacc[ni][1] *= alpha0;
            oacc[ni][2] *= alpha1; oacc[ni][3] *= alpha1;
        }

        // ---- O += P @ V (fp16 2-term; P single fp16) ----
        #pragma unroll
        for (int j = 0; j < 4; j++) {
            uint32_t af[4];
            #pragma unroll
            for (int t = 0; t < 2; t++) {
                af[2*t]   = pack_h2(sacc[2*j+t][0], sacc[2*j+t][1]);
                af[2*t+1] = pack_h2(sacc[2*j+t][2], sacc[2*j+t][3]);
            }
            #pragma unroll
            for (int g = 0; g < 4; g++) {
                const uint32_t off =
                    (uint32_t)((j * 16 + vRow) * FS + g * 16 + vCol) * 2;
                uint32_t vbh[4], vbl[4];
                ldsm_x4_t(vbh, sVh + off);
                ldsm_x4_t(vbl, sVl + off);
                mma16816(oacc[2*g],   af, vbh);
                mma16816(oacc[2*g],   af, vbl);
                mma16816(oacc[2*g+1], af, vbh + 2);
                mma16816(oacc[2*g+1], af, vbl + 2);
            }
        }
    }

    // ---- epilogue: normalize (or vsum/S), write ctx as single fp16 ----
    const float invS = 1.0f / (float)S_;
    const bool dead0 = (m0 == -INFINITY);
    const bool dead1 = (m1 == -INFINITY);
    const float inv0 = dead0 ? 0.f : 1.0f / l0;
    const float inv1 = dead1 ? 0.f : 1.0f / l1;
    const size_t row0 = (size_t)b * S_ + qr0;
    const size_t row1 = (size_t)b * S_ + qr1;
    #pragma unroll
    for (int ni = 0; ni < 8; ni++) {
        const int dd = ni * 8 + colq;
        float v00, v01, v10, v11;
        if (dead0) {
            v00 = g_vsum[bh * DK_ + dd] * invS;
            v01 = g_vsum[bh * DK_ + dd + 1] * invS;
        } else { v00 = oacc[ni][0] * inv0; v01 = oacc[ni][1] * inv0; }
        if (dead1) {
            v10 = g_vsum[bh * DK_ + dd] * invS;
            v11 = g_vsum[bh * DK_ + dd + 1] * invS;
        } else { v10 = oacc[ni][2] * inv1; v11 = oacc[ni][3] * inv1; }

        const size_t o0 = row0 * D_ + h * DK_ + dd;
        const size_t o1 = row1 * D_ + h * DK_ + dd;
        *(__half2*)(g_ch + o0) = __floats2half2_rn(v00, v01);
        *(__half2*)(g_ch + o1) = __floats2half2_rn(v10, v11);
    }
}

// ---------------- launch ------------------------------------------------------
extern "C" void kernel_launch(void* const* d_in, const int* in_sizes, int n_in,
                              void* d_out, int out_size) {
    const float* x   = (const float*)d_in[0];
    const int*   kpm = (const int*)d_in[2];
    const float* Wq  = (const float*)d_in[3];
    const float* Wk  = (const float*)d_in[4];
    const float* Wv  = (const float*)d_in[5];
    const float* Wo  = (const float*)d_in[6];
    const float* bo  = (const float*)d_in[7];
    float* out = (float*)d_out;

    __half *xh, *wh, *wl;
    float* vsum;
    cudaGetSymbolAddress((void**)&xh, g_xh);
    cudaGetSymbolAddress((void**)&wh, g_wh);
    cudaGetSymbolAddress((void**)&wl, g_wl);
    cudaGetSymbolAddress((void**)&vsum, g_vsum);

    cudaFuncSetAttribute(qkv_gemm, cudaFuncAttributeMaxDynamicSharedMemorySize, GEMM_SMEM);
    cudaFuncSetAttribute(out_gemm, cudaFuncAttributeMaxDynamicSharedMemorySize, GEMM_SMEM);
    cudaFuncSetAttribute(flash_mma, cudaFuncAttributeMaxDynamicSharedMemorySize, FLASH_SMEM);

    // 0) zero vsum (capture-safe async memset)
    cudaMemsetAsync(vsum, 0, B_ * H_ * DK_ * sizeof(float));

    // 1) convert x to fp16
    convert_kernel<<<(MROWS * D_ / 4) / 256, 256>>>(x, xh);

    // 2) transpose+split all four weights in one launch
    dim3 tb(32, 8), tg(32, 32, 4);
    transpose_split_kernel<<<tg, tb>>>(Wq, Wk, Wv, Wo, wh, wl);

    // 3) fused Q/K/V projections (N=3072 single GEMM)
    dim3 gq(3 * D_ / 64, MROWS / 128);   // (48, 32)
    qkv_gemm<<<gq, 128, GEMM_SMEM>>>();

    // 4) V row-sums (parallel, atomics)
    dim3 gv(B_ * H_, 8);
    vsum_kernel<<<gv, 256>>>();

    // 5) flash attention (fp16 2-term, 64 q-rows)
    dim3 fg(S_ / 64, B_ * H_);
    flash_mma<<<fg, 128, FLASH_SMEM>>>(kpm);

    // 6) output projection with bias (fp32 out)
    dim3 gg(D_ / 64, MROWS / 128);       // (16, 32)
    out_gemm<<<gg, 128, GEMM_SMEM>>>(bo, out);
}

// round 12
// speedup vs baseline: 1.9937x; 1.4337x over previous
#include <cuda_runtime.h>
#include <cuda_fp16.h>
#include <math.h>
#include <stdint.h>

#define B_  2
#define S_  2048
#define D_  1024
#define H_  16
#define DK_ 64
#define MROWS (B_*S_)      // 4096

// ---------------- scratch (allocation-free: __device__ globals) -------------
__device__ __half g_q[MROWS*D_];
__device__ __half g_k[MROWS*D_];
__device__ __half g_v[MROWS*D_];
__device__ __half g_c[MROWS*D_];           // ctx
__device__ __half g_x[MROWS*D_];
__device__ __half g_w[4*D_*D_];            // W^T [N,K], 4 matrices contiguous
__device__ float g_vsum[B_*H_*DK_];

// ======================= helpers =============================================
__device__ __forceinline__ uint32_t smem_u32(const void* p) {
    uint32_t a;
    asm("{ .reg .u64 t; cvta.to.shared.u64 t, %1; cvt.u32.u64 %0, t; }"
        : "=r"(a) : "l"(p));
    return a;
}
__device__ __forceinline__ void ldsm_x4(uint32_t* r, uint32_t addr) {
    asm volatile("ldmatrix.sync.aligned.m8n8.x4.shared.b16 {%0,%1,%2,%3}, [%4];"
                 : "=r"(r[0]), "=r"(r[1]), "=r"(r[2]), "=r"(r[3]) : "r"(addr));
}
__device__ __forceinline__ void ldsm_x4_t(uint32_t* r, uint32_t addr) {
    asm volatile("ldmatrix.sync.aligned.m8n8.x4.trans.shared.b16 {%0,%1,%2,%3}, [%4];"
                 : "=r"(r[0]), "=r"(r[1]), "=r"(r[2]), "=r"(r[3]) : "r"(addr));
}
__device__ __forceinline__ void mma16816(float* c, const uint32_t* a, const uint32_t* b) {
    asm volatile("mma.sync.aligned.m16n8k16.row.col.f32.f16.f16.f32 "
                 "{%0,%1,%2,%3}, {%4,%5,%6,%7}, {%8,%9}, {%0,%1,%2,%3};"
                 : "+f"(c[0]), "+f"(c[1]), "+f"(c[2]), "+f"(c[3])
                 : "r"(a[0]), "r"(a[1]), "r"(a[2]), "r"(a[3]),
                   "r"(b[0]), "r"(b[1]));
}
__device__ __forceinline__ uint32_t pack_h2(float a, float b) {
    __half2 t = __floats2half2_rn(a, b);
    return *(uint32_t*)&t;
}

// ======================= preprocessing kernels ==============================
__global__ void convert_kernel(const float* __restrict__ src,
                               __half* __restrict__ dst) {
    int i = blockIdx.x * blockDim.x + threadIdx.x;
    float4 v = ((const float4*)src)[i];
    __half2* dp = (__half2*)(dst + 4 * (size_t)i);
    dp[0] = __floats2half2_rn(v.x, v.y);
    dp[1] = __floats2half2_rn(v.z, v.w);
}

// 4 weight transposes in one launch: W[K,N] f32 -> WT[N,K] fp16
__global__ void transpose_kernel(const float* __restrict__ W0,
                                 const float* __restrict__ W1,
                                 const float* __restrict__ W2,
                                 const float* __restrict__ W3,
                                 __half* __restrict__ TB) {
    __shared__ float t[32][33];
    const int z = blockIdx.z;
    const float* W = (z == 0) ? W0 : (z == 1) ? W1 : (z == 2) ? W2 : W3;
    __half* T = TB + (size_t)z * D_ * D_;
    const int n0 = blockIdx.x * 32, k0 = blockIdx.y * 32;
    for (int j = threadIdx.y; j < 32; j += 8)
        t[j][threadIdx.x] = W[(size_t)(k0 + j) * D_ + n0 + threadIdx.x];
    __syncthreads();
    for (int j = threadIdx.y; j < 32; j += 8) {
        float v = t[threadIdx.x][j];
        T[(size_t)(n0 + j) * D_ + k0 + threadIdx.x] = __float2half(v);
    }
}

// ======================= fp16 single GEMM ====================================
// C = A @ B^T, fp32 accumulate. 128 threads, tile 128(M)x64(N),
// warps 2m x 2n, warp tile 64x32. KC=64 single buffer, LDG->STS staging.
#define KC   64
#define SSTR 72
#define SM_A (128 * SSTR)
#define SM_B (64 * SSTR)
#define GEMM_SMEM ((SM_A + SM_B) * 2)    // 27648 B

__device__ __forceinline__ void gemm_mainloop(const __half* __restrict__ A,
                                              const __half* __restrict__ Bp,
                                              __half* smb,
                                              int rowBase, int colBase,
                                              float acc[4][4][4]) {
    __half* As = smb;
    __half* Bs = As + SM_A;

    const int tid  = threadIdx.x;
    const int lane = tid & 31;
    const int wid  = tid >> 5;
    const int wm   = wid >> 1;
    const int wn   = wid & 1;

    const uint32_t sA = smem_u32(As);
    const uint32_t sB = smem_u32(Bs);

    const int r0 = tid >> 3;
    const int cs = (tid & 7) * 8;

    const int aRow = ((lane & 8) ? 8 : 0) + (lane & 7);
    const int aK   = ((lane & 16) ? 8 : 0);
    const int bRow = ((lane & 16) ? 8 : 0) + (lane & 7);
    const int bK   = ((lane & 8) ? 8 : 0);

    for (int c = 0; c < 16; c++) {
        const int kb = c * KC;
        if (c) __syncthreads();
        #pragma unroll
        for (int u = 0; u < 8; u++) {
            const int r = u * 16 + r0;
            const size_t ga = (size_t)(rowBase + r) * D_ + kb + cs;
            *(uint4*)(As + r * SSTR + cs) = *(const uint4*)(A + ga);
        }
        #pragma unroll
        for (int u = 0; u < 4; u++) {
            const int r = u * 16 + r0;
            const size_t gb = (size_t)(colBase + r) * D_ + kb + cs;
            *(uint4*)(Bs + r * SSTR + cs) = *(const uint4*)(Bp + gb);
        }
        __syncthreads();

        #pragma unroll
        for (int k16 = 0; k16 < 4; k16++) {
            const int kk = k16 * 16;
            uint32_t bfr[4][2];
            #pragma unroll
            for (int g = 0; g < 2; g++) {
                const uint32_t off =
                    (uint32_t)((wn * 32 + g * 16 + bRow) * SSTR + kk + bK) * 2;
                uint32_t t4[4];
                ldsm_x4(t4, sB + off);
                bfr[2*g][0] = t4[0]; bfr[2*g][1] = t4[1];
                bfr[2*g+1][0] = t4[2]; bfr[2*g+1][1] = t4[3];
            }
            #pragma unroll
            for (int mi = 0; mi < 4; mi++) {
                const uint32_t offA =
                    (uint32_t)((wm * 64 + mi * 16 + aRow) * SSTR + kk + aK) * 2;
                uint32_t ah[4];
                ldsm_x4(ah, sA + offA);
                #pragma unroll
                for (int ni = 0; ni < 4; ni++)
                    mma16816(acc[mi][ni], ah, bfr[ni]);
            }
        }
    }
}

// fused QKV: single GEMM vs [3072,1024] weight block; z = colBase>>10
__global__ void __launch_bounds__(128) qkv_gemm() {
    extern __shared__ __half smb[];
    const int rowBase = blockIdx.y * 128;
    const int colBase = blockIdx.x * 64;       // [0, 3072)
    const int z = colBase >> 10;               // 0=Q 1=K 2=V
    const int colLoc = colBase & 1023;
    __half* C = (z == 0) ? g_q : (z == 1) ? g_k : g_v;

    float acc[4][4][4];
    #pragma unroll
    for (int i = 0; i < 4; i++)
        #pragma unroll
        for (int j = 0; j < 4; j++)
            #pragma unroll
            for (int q = 0; q < 4; q++) acc[i][j][q] = 0.f;

    gemm_mainloop(g_x, g_w, smb, rowBase, colBase, acc);

    const int lane = threadIdx.x & 31;
    const int wid  = threadIdx.x >> 5;
    const int wm   = wid >> 1;
    const int wn   = wid & 1;
    const int qr = lane >> 2;
    const int qc = (lane & 3) * 2;
    #pragma unroll
    for (int mi = 0; mi < 4; mi++) {
        const int m0 = rowBase + wm * 64 + mi * 16 + qr;
        #pragma unroll
        for (int ni = 0; ni < 4; ni++) {
            const int cc = colLoc + wn * 32 + ni * 8 + qc;
            #pragma unroll
            for (int rr = 0; rr < 2; rr++) {
                const size_t o = (size_t)(m0 + rr * 8) * D_ + cc;
                *(__half2*)(C + o) = __floats2half2_rn(acc[mi][ni][rr*2+0],
                                                       acc[mi][ni][rr*2+1]);
            }
        }
    }
}

// output projection with bias, fp32 out
__global__ void __launch_bounds__(128) out_gemm(const float* __restrict__ bias,
                                                float* __restrict__ C) {
    extern __shared__ __half smb[];
    const int rowBase = blockIdx.y * 128;
    const int colBase = blockIdx.x * 64;

    float acc[4][4][4];
    #pragma unroll
    for (int i = 0; i < 4; i++)
        #pragma unroll
        for (int j = 0; j < 4; j++)
            #pragma unroll
            for (int q = 0; q < 4; q++) acc[i][j][q] = 0.f;

    gemm_mainloop(g_c, g_w + 3 * (size_t)D_ * D_, smb, rowBase, colBase, acc);

    const int lane = threadIdx.x & 31;
    const int wid  = threadIdx.x >> 5;
    const int wm   = wid >> 1;
    const int wn   = wid & 1;
    const int qr = lane >> 2;
    const int qc = (lane & 3) * 2;
    #pragma unroll
    for (int mi = 0; mi < 4; mi++) {
        const int m0 = rowBase + wm * 64 + mi * 16 + qr;
        #pragma unroll
        for (int ni = 0; ni < 4; ni++) {
            const int cc = colBase + wn * 32 + ni * 8 + qc;
            float b0 = bias[cc], b1 = bias[cc + 1];
            float2 v0; v0.x = acc[mi][ni][0] + b0; v0.y = acc[mi][ni][1] + b1;
            float2 v1; v1.x = acc[mi][ni][2] + b0; v1.y = acc[mi][ni][3] + b1;
            *(float2*)&C[(size_t)m0 * D_ + cc] = v0;
            *(float2*)&C[(size_t)(m0 + 8) * D_ + cc] = v1;
        }
    }
}

// ---------------- per-(b,h) V row-sum: 8 partial blocks per bh + atomics -----
__global__ void vsum_kernel() {
    __shared__ float red[256];
    const int bh = blockIdx.x;
    const int part = blockIdx.y;
    const int b  = bh / H_, h = bh % H_;
    const int dk = threadIdx.x & 63;
    const int grp = threadIdx.x >> 6;
    const __half* Vp = g_v + (size_t)b * S_ * D_ + h * DK_ + dk;
    float s = 0.f;
    const int base = part * 256 + grp * 64;
    for (int i = 0; i < 64; i++)
        s += __half2float(Vp[(size_t)(base + i) * D_]);
    red[threadIdx.x] = s;
    __syncthreads();
    if (threadIdx.x < 64) {
        float t = red[threadIdx.x] + red[threadIdx.x + 64]
                + red[threadIdx.x + 128] + red[threadIdx.x + 192];
        atomicAdd(&g_vsum[bh * DK_ + threadIdx.x], t);
    }
}

// ================= flash attention (fp16 single, 64 q-rows) ==================
#define FS 72
#define FLASH_SMEM (3 * 64 * FS * 2 + 64 * 4)    // 27904 B

__global__ void __launch_bounds__(128) flash_mma(const int* __restrict__ kpm) {
    extern __shared__ __half fsm[];
    __half* Qs = fsm;                    // 64 x FS
    __half* Ks = Qs + 64 * FS;
    __half* Vs = Ks + 64 * FS;
    int* pads = (int*)(Vs + 64 * FS);

    const int tid  = threadIdx.x;
    const int lane = tid & 31;
    const int wq   = tid >> 5;
    const int qblk = (int)gridDim.x - 1 - (int)blockIdx.x;   // big tiles first
    const int bh   = blockIdx.y;
    const int b = bh / H_, h = bh % H_;

    const uint32_t sQ = smem_u32(Qs);
    const uint32_t sK = smem_u32(Ks);
    const uint32_t sV = smem_u32(Vs);

    const size_t headOff = (size_t)b * S_ * D_ + h * DK_;
    const size_t qOff = headOff + (size_t)(qblk * 64) * D_;

    // load Q tile (64 x 64 fp16): 4096 halfs = 512 uint4, 128 thr -> 4 each
    #pragma unroll
    for (int u = 0; u < 4; u++) {
        const int idx = u * 128 + tid;
        const int r = idx >> 3, c = (idx & 7) * 8;
        *(uint4*)(Qs + r * FS + c) = *(const uint4*)(g_q + qOff + (size_t)r * D_ + c);
    }

    const int aRow = ((lane & 8) ? 8 : 0) + (lane & 7);
    const int aK   = ((lane & 16) ? 8 : 0);
    const int bRow = ((lane & 16) ? 8 : 0) + (lane & 7);
    const int bK   = ((lane & 8) ? 8 : 0);
    const int vRow = ((lane & 8) ? 8 : 0) + (lane & 7);
    const int vCol = ((lane & 16) ? 8 : 0);

    float m0 = -INFINITY, m1 = -INFINITY, l0 = 0.f, l1 = 0.f;
    float oacc[8][4];
    #pragma unroll
    for (int ni = 0; ni < 8; ni++)
        #pragma unroll
        for (int q = 0; q < 4; q++) oacc[ni][q] = 0.f;

    const int qr0 = qblk * 64 + wq * 16 + (lane >> 2);
    const int qr1 = qr0 + 8;
    const int colq = (lane & 3) * 2;

    for (int kt = 0; kt <= qblk; kt++) {
        __syncthreads();
        {
            const size_t kOff = headOff + (size_t)(kt * 64) * D_;
            #pragma unroll
            for (int u = 0; u < 4; u++) {
                const int idx = u * 128 + tid;
                const int r = idx >> 3, c = (idx & 7) * 8;
                const size_t go = kOff + (size_t)r * D_ + c;
                const int so = r * FS + c;
                *(uint4*)(Ks + so) = *(const uint4*)(g_k + go);
                *(uint4*)(Vs + so) = *(const uint4*)(g_v + go);
            }
            if (tid < 64) pads[tid] = kpm[b * S_ + kt * 64 + tid];
        }
        __syncthreads();

        // ---- S = Q @ K^T ----
        float sacc[8][4];
        #pragma unroll
        for (int ni = 0; ni < 8; ni++)
            #pragma unroll
            for (int q = 0; q < 4; q++) sacc[ni][q] = 0.f;

        #pragma unroll
        for (int j = 0; j < 4; j++) {
            const int kk = j * 16;
            uint32_t ah[4];
            ldsm_x4(ah, sQ + (uint32_t)((wq * 16 + aRow) * FS + kk + aK) * 2);
            #pragma unroll
            for (int g = 0; g < 4; g++) {
                const uint32_t off = (uint32_t)((g * 16 + bRow) * FS + kk + bK) * 2;
                uint32_t th[4];
                ldsm_x4(th, sK + off);
                mma16816(sacc[2*g],   ah, th);
                mma16816(sacc[2*g+1], ah, th + 2);
            }
        }

        // ---- mask + scale ----
        const bool diag = (kt == qblk);
        #pragma unroll
        for (int ni = 0; ni < 8; ni++) {
            const int kc = kt * 64 + ni * 8 + colq;
            const int p0 = pads[ni * 8 + colq];
            const int p1 = pads[ni * 8 + colq + 1];
            bool v00 = !p0, v01 = !p1, v10 = !p0, v11 = !p1;
            if (diag) {
                v00 = v00 && (kc     <= qr0);
                v01 = v01 && (kc + 1 <= qr0);
                v10 = v10 && (kc     <= qr1);
                v11 = v11 && (kc + 1 <= qr1);
            }
            sacc[ni][0] = v00 ? sacc[ni][0] * 0.125f : -INFINITY;
            sacc[ni][1] = v01 ? sacc[ni][1] * 0.125f : -INFINITY;
            sacc[ni][2] = v10 ? sacc[ni][2] * 0.125f : -INFINITY;
            sacc[ni][3] = v11 ? sacc[ni][3] * 0.125f : -INFINITY;
        }

        // ---- online softmax ----
        float mt0 = -INFINITY, mt1 = -INFINITY;
        #pragma unroll
        for (int ni = 0; ni < 8; ni++) {
            mt0 = fmaxf(mt0, fmaxf(sacc[ni][0], sacc[ni][1]));
            mt1 = fmaxf(mt1, fmaxf(sacc[ni][2], sacc[ni][3]));
        }
        mt0 = fmaxf(mt0, __shfl_xor_sync(0xffffffffu, mt0, 1));
        mt0 = fmaxf(mt0, __shfl_xor_sync(0xffffffffu, mt0, 2));
        mt1 = fmaxf(mt1, __shfl_xor_sync(0xffffffffu, mt1, 1));
        mt1 = fmaxf(mt1, __shfl_xor_sync(0xffffffffu, mt1, 2));

        const float mn0 = fmaxf(m0, mt0);
        const float mn1 = fmaxf(m1, mt1);
        const bool live0 = (mn0 != -INFINITY);
        const bool live1 = (mn1 != -INFINITY);
        const float alpha0 = live0 ? __expf(m0 - mn0) : 1.f;
        const float alpha1 = live1 ? __expf(m1 - mn1) : 1.f;

        float ps0 = 0.f, ps1 = 0.f;
        #pragma unroll
        for (int ni = 0; ni < 8; ni++) {
            float p00 = live0 ? __expf(sacc[ni][0] - mn0) : 0.f;
            float p01 = live0 ? __expf(sacc[ni][1] - mn0) : 0.f;
            float p10 = live1 ? __expf(sacc[ni][2] - mn1) : 0.f;
            float p11 = live1 ? __expf(sacc[ni][3] - mn1) : 0.f;
            sacc[ni][0] = p00; sacc[ni][1] = p01;
            sacc[ni][2] = p10; sacc[ni][3] = p11;
            ps0 += p00 + p01;
            ps1 += p10 + p11;
        }
        ps0 += __shfl_xor_sync(0xffffffffu, ps0, 1);
        ps0 += __shfl_xor_sync(0xffffffffu, ps0, 2);
        ps1 += __shfl_xor_sync(0xffffffffu, ps1, 1);
        ps1 += __shfl_xor_sync(0xffffffffu, ps1, 2);

        l0 = l0 * alpha0 + ps0;
        l1 = l1 * alpha1 + ps1;
        m0 = mn0; m1 = mn1;
        #pragma unroll
        for (int ni = 0; ni < 8; ni++) {
            oacc[ni][0] *= alpha0; oacc[ni][1] *= alpha0;
            oacc[ni][2] *= alpha1; oacc[ni][3] *= alpha1;
        }

        // ---- O += P @ V ----
        #pragma unroll
        for (int j = 0; j < 4; j++) {
            uint32_t af[4];
            #pragma unroll
            for (int t = 0; t < 2; t++) {
                af[2*t]   = pack_h2(sacc[2*j+t][0], sacc[2*j+t][1]);
                af[2*t+1] = pack_h2(sacc[2*j+t][2], sacc[2*j+t][3]);
            }
            #pragma unroll
            for (int g = 0; g < 4; g++) {
                const uint32_t off =
                    (uint32_t)((j * 16 + vRow) * FS + g * 16 + vCol) * 2;
                uint32_t vb[4];
                ldsm_x4_t(vb, sV + off);
                mma16816(oacc[2*g],   af, vb);
                mma16816(oacc[2*g+1], af, vb + 2);
            }
        }
    }

    // ---- epilogue: normalize (or vsum/S), write ctx fp16 ----
    const float invS = 1.0f / (float)S_;
    const bool dead0 = (m0 == -INFINITY);
    const bool dead1 = (m1 == -INFINITY);
    const float inv0 = dead0 ? 0.f : 1.0f / l0;
    const float inv1 = dead1 ? 0.f : 1.0f / l1;
    const size_t row0 = (size_t)b * S_ + qr0;
    const size_t row1 = (size_t)b * S_ + qr1;
    #pragma unroll
    for (int ni = 0; ni < 8; ni++) {
        const int dd = ni * 8 + colq;
        float v00, v01, v10, v11;
        if (dead0) {
            v00 = g_vsum[bh * DK_ + dd] * invS;
            v01 = g_vsum[bh * DK_ + dd + 1] * invS;
        } else { v00 = oacc[ni][0] * inv0; v01 = oacc[ni][1] * inv0; }
        if (dead1) {
            v10 = g_vsum[bh * DK_ + dd] * invS;
            v11 = g_vsum[bh * DK_ + dd + 1] * invS;
        } else { v10 = oacc[ni][2] * inv1; v11 = oacc[ni][3] * inv1; }

        const size_t o0 = row0 * D_ + h * DK_ + dd;
        const size_t o1 = row1 * D_ + h * DK_ + dd;
        *(__half2*)(g_c + o0) = __floats2half2_rn(v00, v01);
        *(__half2*)(g_c + o1) = __floats2half2_rn(v10, v11);
    }
}

// ---------------- launch ------------------------------------------------------
extern "C" void kernel_launch(void* const* d_in, const int* in_sizes, int n_in,
                              void* d_out, int out_size) {
    const float* x   = (const float*)d_in[0];
    const int*   kpm = (const int*)d_in[2];
    const float* Wq  = (const float*)d_in[3];
    const float* Wk  = (const float*)d_in[4];
    const float* Wv  = (const float*)d_in[5];
    const float* Wo  = (const float*)d_in[6];
    const float* bo  = (const float*)d_in[7];
    float* out = (float*)d_out;

    __half *xh, *wh;
    float* vsum;
    cudaGetSymbolAddress((void**)&xh, g_x);
    cudaGetSymbolAddress((void**)&wh, g_w);
    cudaGetSymbolAddress((void**)&vsum, g_vsum);

    cudaFuncSetAttribute(qkv_gemm, cudaFuncAttributeMaxDynamicSharedMemorySize, GEMM_SMEM);
    cudaFuncSetAttribute(out_gemm, cudaFuncAttributeMaxDynamicSharedMemorySize, GEMM_SMEM);
    cudaFuncSetAttribute(flash_mma, cudaFuncAttributeMaxDynamicSharedMemorySize, FLASH_SMEM);

    // 0) zero vsum (capture-safe async memset)
    cudaMemsetAsync(vsum, 0, B_ * H_ * DK_ * sizeof(float));

    // 1) convert x to fp16
    convert_kernel<<<(MROWS * D_ / 4) / 256, 256>>>(x, xh);

    // 2) transpose all four weights in one launch
    dim3 tb(32, 8), tg(32, 32, 4);
    transpose_kernel<<<tg, tb>>>(Wq, Wk, Wv, Wo, wh);

    // 3) fused Q/K/V projections (N=3072 single GEMM)
    dim3 gq(3 * D_ / 64, MROWS / 128);   // (48, 32)
    qkv_gemm<<<gq, 128, GEMM_SMEM>>>();

    // 4) V row-sums (parallel, atomics)
    dim3 gv(B_ * H_, 8);
    vsum_kernel<<<gv, 256>>>();

    // 5) flash attention (fp16 single, 64 q-rows)
    dim3 fg(S_ / 64, B_ * H_);
    flash_mma<<<fg, 128, FLASH_SMEM>>>(kpm);

    // 6) output projection with bias (fp32 out)
    dim3 gg(D_ / 64, MROWS / 128);       // (16, 32)
    out_gemm<<<gg, 128, GEMM_SMEM>>>(bo, out);
}

// round 13
// speedup vs baseline: 2.0973x; 1.0520x over previous
#include <cuda_runtime.h>
#include <cuda_fp16.h>
#include <math.h>
#include <stdint.h>

#define B_  2
#define S_  2048
#define D_  1024
#define H_  16
#define DK_ 64
#define MROWS (B_*S_)      // 4096

// ---------------- scratch (allocation-free: __device__ globals) -------------
__device__ __half g_q[MROWS*D_];
__device__ __half g_k[MROWS*D_];
__device__ __half g_v[MROWS*D_];
__device__ __half g_c[MROWS*D_];           // ctx
__device__ __half g_x[MROWS*D_];
__device__ __half g_w[4*D_*D_];            // W^T [N,K], 4 matrices contiguous
__device__ float g_vsum[B_*H_*DK_];

// ======================= helpers =============================================
__device__ __forceinline__ uint32_t smem_u32(const void* p) {
    uint32_t a;
    asm("{ .reg .u64 t; cvta.to.shared.u64 t, %1; cvt.u32.u64 %0, t; }"
        : "=r"(a) : "l"(p));
    return a;
}
__device__ __forceinline__ void ldsm_x4(uint32_t* r, uint32_t addr) {
    asm volatile("ldmatrix.sync.aligned.m8n8.x4.shared.b16 {%0,%1,%2,%3}, [%4];"
                 : "=r"(r[0]), "=r"(r[1]), "=r"(r[2]), "=r"(r[3]) : "r"(addr));
}
__device__ __forceinline__ void ldsm_x4_t(uint32_t* r, uint32_t addr) {
    asm volatile("ldmatrix.sync.aligned.m8n8.x4.trans.shared.b16 {%0,%1,%2,%3}, [%4];"
                 : "=r"(r[0]), "=r"(r[1]), "=r"(r[2]), "=r"(r[3]) : "r"(addr));
}
__device__ __forceinline__ void mma16816(float* c, const uint32_t* a, const uint32_t* b) {
    asm volatile("mma.sync.aligned.m16n8k16.row.col.f32.f16.f16.f32 "
                 "{%0,%1,%2,%3}, {%4,%5,%6,%7}, {%8,%9}, {%0,%1,%2,%3};"
                 : "+f"(c[0]), "+f"(c[1]), "+f"(c[2]), "+f"(c[3])
                 : "r"(a[0]), "r"(a[1]), "r"(a[2]), "r"(a[3]),
                   "r"(b[0]), "r"(b[1]));
}
__device__ __forceinline__ uint32_t pack_h2(float a, float b) {
    __half2 t = __floats2half2_rn(a, b);
    return *(uint32_t*)&t;
}

// ======================= preprocessing kernels ==============================
__global__ void convert_kernel(const float* __restrict__ src,
                               __half* __restrict__ dst) {
    int i = blockIdx.x * blockDim.x + threadIdx.x;
    float4 v = ((const float4*)src)[i];
    __half2* dp = (__half2*)(dst + 4 * (size_t)i);
    dp[0] = __floats2half2_rn(v.x, v.y);
    dp[1] = __floats2half2_rn(v.z, v.w);
}

// 4 weight transposes in one launch: W[K,N] f32 -> WT[N,K] fp16
__global__ void transpose_kernel(const float* __restrict__ W0,
                                 const float* __restrict__ W1,
                                 const float* __restrict__ W2,
                                 const float* __restrict__ W3,
                                 __half* __restrict__ TB) {
    __shared__ float t[32][33];
    const int z = blockIdx.z;
    const float* W = (z == 0) ? W0 : (z == 1) ? W1 : (z == 2) ? W2 : W3;
    __half* T = TB + (size_t)z * D_ * D_;
    const int n0 = blockIdx.x * 32, k0 = blockIdx.y * 32;
    for (int j = threadIdx.y; j < 32; j += 8)
        t[j][threadIdx.x] = W[(size_t)(k0 + j) * D_ + n0 + threadIdx.x];
    __syncthreads();
    for (int j = threadIdx.y; j < 32; j += 8) {
        float v = t[threadIdx.x][j];
        T[(size_t)(n0 + j) * D_ + k0 + threadIdx.x] = __float2half(v);
    }
}

// ======================= fp16 single GEMM ====================================
#define KC   64
#define SSTR 72
#define SM_A (128 * SSTR)
#define SM_B (64 * SSTR)
#define GEMM_SMEM ((SM_A + SM_B) * 2)    // 27648 B

__device__ __forceinline__ void gemm_mainloop(const __half* __restrict__ A,
                                              const __half* __restrict__ Bp,
                                              __half* smb,
                                              int rowBase, int colBase,
                                              float acc[4][4][4]) {
    __half* As = smb;
    __half* Bs = As + SM_A;

    const int tid  = threadIdx.x;
    const int lane = tid & 31;
    const int wid  = tid >> 5;
    const int wm   = wid >> 1;
    const int wn   = wid & 1;

    const uint32_t sA = smem_u32(As);
    const uint32_t sB = smem_u32(Bs);

    const int r0 = tid >> 3;
    const int cs = (tid & 7) * 8;

    const int aRow = ((lane & 8) ? 8 : 0) + (lane & 7);
    const int aK   = ((lane & 16) ? 8 : 0);
    const int bRow = ((lane & 16) ? 8 : 0) + (lane & 7);
    const int bK   = ((lane & 8) ? 8 : 0);

    for (int c = 0; c < 16; c++) {
        const int kb = c * KC;
        if (c) __syncthreads();
        #pragma unroll
        for (int u = 0; u < 8; u++) {
            const int r = u * 16 + r0;
            const size_t ga = (size_t)(rowBase + r) * D_ + kb + cs;
            *(uint4*)(As + r * SSTR + cs) = *(const uint4*)(A + ga);
        }
        #pragma unroll
        for (int u = 0; u < 4; u++) {
            const int r = u * 16 + r0;
            const size_t gb = (size_t)(colBase + r) * D_ + kb + cs;
            *(uint4*)(Bs + r * SSTR + cs) = *(const uint4*)(Bp + gb);
        }
        __syncthreads();

        #pragma unroll
        for (int k16 = 0; k16 < 4; k16++) {
            const int kk = k16 * 16;
            uint32_t bfr[4][2];
            #pragma unroll
            for (int g = 0; g < 2; g++) {
                const uint32_t off =
                    (uint32_t)((wn * 32 + g * 16 + bRow) * SSTR + kk + bK) * 2;
                uint32_t t4[4];
                ldsm_x4(t4, sB + off);
                bfr[2*g][0] = t4[0]; bfr[2*g][1] = t4[1];
                bfr[2*g+1][0] = t4[2]; bfr[2*g+1][1] = t4[3];
            }
            #pragma unroll
            for (int mi = 0; mi < 4; mi++) {
                const uint32_t offA =
                    (uint32_t)((wm * 64 + mi * 16 + aRow) * SSTR + kk + aK) * 2;
                uint32_t ah[4];
                ldsm_x4(ah, sA + offA);
                #pragma unroll
                for (int ni = 0; ni < 4; ni++)
                    mma16816(acc[mi][ni], ah, bfr[ni]);
            }
        }
    }
}

// fused QKV + fused V-column-sum (for dead-row fallback)
__global__ void __launch_bounds__(128) qkv_gemm() {
    extern __shared__ __half smb[];
    const int rowBase = blockIdx.y * 128;
    const int colBase = blockIdx.x * 64;       // [0, 3072)
    const int z = colBase >> 10;               // 0=Q 1=K 2=V
    const int colLoc = colBase & 1023;
    __half* C = (z == 0) ? g_q : (z == 1) ? g_k : g_v;

    float acc[4][4][4];
    #pragma unroll
    for (int i = 0; i < 4; i++)
        #pragma unroll
        for (int j = 0; j < 4; j++)
            #pragma unroll
            for (int q = 0; q < 4; q++) acc[i][j][q] = 0.f;

    gemm_mainloop(g_x, g_w, smb, rowBase, colBase, acc);

    const int lane = threadIdx.x & 31;
    const int wid  = threadIdx.x >> 5;
    const int wm   = wid >> 1;
    const int wn   = wid & 1;
    const int qr = lane >> 2;
    const int qc = (lane & 3) * 2;
    #pragma unroll
    for (int mi = 0; mi < 4; mi++) {
        const int m0 = rowBase + wm * 64 + mi * 16 + qr;
        #pragma unroll
        for (int ni = 0; ni < 4; ni++) {
            const int cc = colLoc + wn * 32 + ni * 8 + qc;
            #pragma unroll
            for (int rr = 0; rr < 2; rr++) {
                const size_t o = (size_t)(m0 + rr * 8) * D_ + cc;
                *(__half2*)(C + o) = __floats2half2_rn(acc[mi][ni][rr*2+0],
                                                       acc[mi][ni][rr*2+1]);
            }
        }
    }

    // fused vsum: V tiles accumulate their 128-row column sums
    if (z == 2) {
        const int b = rowBase >> 11;           // 2048 rows per batch
        const int h = colLoc >> 6;             // 64 cols per head
        #pragma unroll
        for (int ni = 0; ni < 4; ni++) {
            float c0 = 0.f, c1 = 0.f;
            #pragma unroll
            for (int mi = 0; mi < 4; mi++) {
                c0 += acc[mi][ni][0] + acc[mi][ni][2];
                c1 += acc[mi][ni][1] + acc[mi][ni][3];
            }
            c0 += __shfl_xor_sync(0xffffffffu, c0, 4);
            c0 += __shfl_xor_sync(0xffffffffu, c0, 8);
            c0 += __shfl_xor_sync(0xffffffffu, c0, 16);
            c1 += __shfl_xor_sync(0xffffffffu, c1, 4);
            c1 += __shfl_xor_sync(0xffffffffu, c1, 8);
            c1 += __shfl_xor_sync(0xffffffffu, c1, 16);
            if (qr == 0) {
                const int dd = wn * 32 + ni * 8 + qc;
                atomicAdd(&g_vsum[(b * H_ + h) * DK_ + dd], c0);
                atomicAdd(&g_vsum[(b * H_ + h) * DK_ + dd + 1], c1);
            }
        }
    }
}

// output projection with bias, fp32 out
__global__ void __launch_bounds__(128) out_gemm(const float* __restrict__ bias,
                                                float* __restrict__ C) {
    extern __shared__ __half smb[];
    const int rowBase = blockIdx.y * 128;
    const int colBase = blockIdx.x * 64;

    float acc[4][4][4];
    #pragma unroll
    for (int i = 0; i < 4; i++)
        #pragma unroll
        for (int j = 0; j < 4; j++)
            #pragma unroll
            for (int q = 0; q < 4; q++) acc[i][j][q] = 0.f;

    gemm_mainloop(g_c, g_w + 3 * (size_t)D_ * D_, smb, rowBase, colBase, acc);

    const int lane = threadIdx.x & 31;
    const int wid  = threadIdx.x >> 5;
    const int wm   = wid >> 1;
    const int wn   = wid & 1;
    const int qr = lane >> 2;
    const int qc = (lane & 3) * 2;
    #pragma unroll
    for (int mi = 0; mi < 4; mi++) {
        const int m0 = rowBase + wm * 64 + mi * 16 + qr;
        #pragma unroll
        for (int ni = 0; ni < 4; ni++) {
            const int cc = colBase + wn * 32 + ni * 8 + qc;
            float b0 = bias[cc], b1 = bias[cc + 1];
            float2 v0; v0.x = acc[mi][ni][0] + b0; v0.y = acc[mi][ni][1] + b1;
            float2 v1; v1.x = acc[mi][ni][2] + b0; v1.y = acc[mi][ni][3] + b1;
            *(float2*)&C[(size_t)m0 * D_ + cc] = v0;
            *(float2*)&C[(size_t)(m0 + 8) * D_ + cc] = v1;
        }
    }
}

// ================= flash attention (fp16, log2-domain softmax) ===============
// scale = 1/8 (score) * log2(e) so probabilities use exp2 directly
#define FSC 0.180336880f
#define FS 72
#define FLASH_SMEM (3 * 64 * FS * 2 + 64 * 4)    // 27904 B

__global__ void __launch_bounds__(128) flash_mma(const int* __restrict__ kpm) {
    extern __shared__ __half fsm[];
    __half* Qs = fsm;                    // 64 x FS
    __half* Ks = Qs + 64 * FS;
    __half* Vs = Ks + 64 * FS;
    float* padf = (float*)(Vs + 64 * FS);   // 0.0 = valid, -INF = padded

    const int tid  = threadIdx.x;
    const int lane = tid & 31;
    const int wq   = tid >> 5;
    const int qblk = (int)gridDim.x - 1 - (int)blockIdx.x;   // big tiles first
    const int bh   = blockIdx.y;
    const int b = bh / H_, h = bh % H_;

    const uint32_t sQ = smem_u32(Qs);
    const uint32_t sK = smem_u32(Ks);
    const uint32_t sV = smem_u32(Vs);

    const size_t headOff = (size_t)b * S_ * D_ + h * DK_;
    const size_t qOff = headOff + (size_t)(qblk * 64) * D_;

    #pragma unroll
    for (int u = 0; u < 4; u++) {
        const int idx = u * 128 + tid;
        const int r = idx >> 3, c = (idx & 7) * 8;
        *(uint4*)(Qs + r * FS + c) = *(const uint4*)(g_q + qOff + (size_t)r * D_ + c);
    }

    const int aRow = ((lane & 8) ? 8 : 0) + (lane & 7);
    const int aK   = ((lane & 16) ? 8 : 0);
    const int bRow = ((lane & 16) ? 8 : 0) + (lane & 7);
    const int bK   = ((lane & 8) ? 8 : 0);
    const int vRow = ((lane & 8) ? 8 : 0) + (lane & 7);
    const int vCol = ((lane & 16) ? 8 : 0);

    float m0 = -INFINITY, m1 = -INFINITY, l0 = 0.f, l1 = 0.f;
    float oacc[8][4];
    #pragma unroll
    for (int ni = 0; ni < 8; ni++)
        #pragma unroll
        for (int q = 0; q < 4; q++) oacc[ni][q] = 0.f;

    const int qr0 = qblk * 64 + wq * 16 + (lane >> 2);
    const int qr1 = qr0 + 8;
    const int colq = (lane & 3) * 2;

    for (int kt = 0; kt <= qblk; kt++) {
        __syncthreads();
        {
            const size_t kOff = headOff + (size_t)(kt * 64) * D_;
            #pragma unroll
            for (int u = 0; u < 4; u++) {
                const int idx = u * 128 + tid;
                const int r = idx >> 3, c = (idx & 7) * 8;
                const size_t go = kOff + (size_t)r * D_ + c;
                const int so = r * FS + c;
                *(uint4*)(Ks + so) = *(const uint4*)(g_k + go);
                *(uint4*)(Vs + so) = *(const uint4*)(g_v + go);
            }
            if (tid < 64) padf[tid] = kpm[b * S_ + kt * 64 + tid] ? -INFINITY : 0.f;
        }
        __syncthreads();

        // ---- S = Q @ K^T ----
        float sacc[8][4];
        #pragma unroll
        for (int ni = 0; ni < 8; ni++)
            #pragma unroll
            for (int q = 0; q < 4; q++) sacc[ni][q] = 0.f;

        #pragma unroll
        for (int j = 0; j < 4; j++) {
            const int kk = j * 16;
            uint32_t ah[4];
            ldsm_x4(ah, sQ + (uint32_t)((wq * 16 + aRow) * FS + kk + aK) * 2);
            #pragma unroll
            for (int g = 0; g < 4; g++) {
                const uint32_t off = (uint32_t)((g * 16 + bRow) * FS + kk + bK) * 2;
                uint32_t th[4];
                ldsm_x4(th, sK + off);
                mma16816(sacc[2*g],   ah, th);
                mma16816(sacc[2*g+1], ah, th + 2);
            }
        }

        // ---- scale + padding (single FMA per element), causal on diag only --
        const bool diag = (kt == qblk);
        #pragma unroll
        for (int ni = 0; ni < 8; ni++) {
            const float pj0 = padf[ni * 8 + colq];
            const float pj1 = padf[ni * 8 + colq + 1];
            sacc[ni][0] = fmaf(sacc[ni][0], FSC, pj0);
            sacc[ni][1] = fmaf(sacc[ni][1], FSC, pj1);
            sacc[ni][2] = fmaf(sacc[ni][2], FSC, pj0);
            sacc[ni][3] = fmaf(sacc[ni][3], FSC, pj1);
            if (diag) {
                const int kc = kt * 64 + ni * 8 + colq;
                if (kc     > qr0) sacc[ni][0] = -INFINITY;
                if (kc + 1 > qr0) sacc[ni][1] = -INFINITY;
                if (kc     > qr1) sacc[ni][2] = -INFINITY;
                if (kc + 1 > qr1) sacc[ni][3] = -INFINITY;
            }
        }

        // ---- online softmax (log2 domain) ----
        float mt0 = -INFINITY, mt1 = -INFINITY;
        #pragma unroll
        for (int ni = 0; ni < 8; ni++) {
            mt0 = fmaxf(mt0, fmaxf(sacc[ni][0], sacc[ni][1]));
            mt1 = fmaxf(mt1, fmaxf(sacc[ni][2], sacc[ni][3]));
        }
        mt0 = fmaxf(mt0, __shfl_xor_sync(0xffffffffu, mt0, 1));
        mt0 = fmaxf(mt0, __shfl_xor_sync(0xffffffffu, mt0, 2));
        mt1 = fmaxf(mt1, __shfl_xor_sync(0xffffffffu, mt1, 1));
        mt1 = fmaxf(mt1, __shfl_xor_sync(0xffffffffu, mt1, 2));

        const float mn0 = fmaxf(m0, mt0);
        const float mn1 = fmaxf(m1, mt1);
        const bool live0 = (mn0 != -INFINITY);
        const bool live1 = (mn1 != -INFINITY);
        const float alpha0 = live0 ? exp2f(m0 - mn0) : 1.f;
        const float alpha1 = live1 ? exp2f(m1 - mn1) : 1.f;

        float ps0 = 0.f, ps1 = 0.f;
        #pragma unroll
        for (int ni = 0; ni < 8; ni++) {
            float p00 = live0 ? exp2f(sacc[ni][0] - mn0) : 0.f;
            float p01 = live0 ? exp2f(sacc[ni][1] - mn0) : 0.f;
            float p10 = live1 ? exp2f(sacc[ni][2] - mn1) : 0.f;
            float p11 = live1 ? exp2f(sacc[ni][3] - mn1) : 0.f;
            sacc[ni][0] = p00; sacc[ni][1] = p01;
            sacc[ni][2] = p10; sacc[ni][3] = p11;
            ps0 += p00 + p01;
            ps1 += p10 + p11;
        }
        ps0 += __shfl_xor_sync(0xffffffffu, ps0, 1);
        ps0 += __shfl_xor_sync(0xffffffffu, ps0, 2);
        ps1 += __shfl_xor_sync(0xffffffffu, ps1, 1);
        ps1 += __shfl_xor_sync(0xffffffffu, ps1, 2);

        l0 = l0 * alpha0 + ps0;
        l1 = l1 * alpha1 + ps1;
        m0 = mn0; m1 = mn1;
        #pragma unroll
        for (int ni = 0; ni < 8; ni++) {
            oacc[ni][0] *= alpha0; oacc[ni][1] *= alpha0;
            oacc[ni][2] *= alpha1; oacc[ni][3] *= alpha1;
        }

        // ---- O += P @ V ----
        #pragma unroll
        for (int j = 0; j < 4; j++) {
            uint32_t af[4];
            #pragma unroll
            for (int t = 0; t < 2; t++) {
                af[2*t]   = pack_h2(sacc[2*j+t][0], sacc[2*j+t][1]);
                af[2*t+1] = pack_h2(sacc[2*j+t][2], sacc[2*j+t][3]);
            }
            #pragma unroll
            for (int g = 0; g < 4; g++) {
                const uint32_t off =
                    (uint32_t)((j * 16 + vRow) * FS + g * 16 + vCol) * 2;
                uint32_t vb[4];
                ldsm_x4_t(vb, sV + off);
                mma16816(oacc[2*g],   af, vb);
                mma16816(oacc[2*g+1], af, vb + 2);
            }
        }
    }

    // ---- epilogue ----
    const float invS = 1.0f / (float)S_;
    const bool dead0 = (m0 == -INFINITY);
    const bool dead1 = (m1 == -INFINITY);
    const float inv0 = dead0 ? 0.f : 1.0f / l0;
    const float inv1 = dead1 ? 0.f : 1.0f / l1;
    const size_t row0 = (size_t)b * S_ + qr0;
    const size_t row1 = (size_t)b * S_ + qr1;
    #pragma unroll
    for (int ni = 0; ni < 8; ni++) {
        const int dd = ni * 8 + colq;
        float v00, v01, v10, v11;
        if (dead0) {
            v00 = g_vsum[bh * DK_ + dd] * invS;
            v01 = g_vsum[bh * DK_ + dd + 1] * invS;
        } else { v00 = oacc[ni][0] * inv0; v01 = oacc[ni][1] * inv0; }
        if (dead1) {
            v10 = g_vsum[bh * DK_ + dd] * invS;
            v11 = g_vsum[bh * DK_ + dd + 1] * invS;
        } else { v10 = oacc[ni][2] * inv1; v11 = oacc[ni][3] * inv1; }

        const size_t o0 = row0 * D_ + h * DK_ + dd;
        const size_t o1 = row1 * D_ + h * DK_ + dd;
        *(__half2*)(g_c + o0) = __floats2half2_rn(v00, v01);
        *(__half2*)(g_c + o1) = __floats2half2_rn(v10, v11);
    }
}

// ---------------- launch ------------------------------------------------------
extern "C" void kernel_launch(void* const* d_in, const int* in_sizes, int n_in,
                              void* d_out, int out_size) {
    const float* x   = (const float*)d_in[0];
    const int*   kpm = (const int*)d_in[2];
    const float* Wq  = (const float*)d_in[3];
    const float* Wk  = (const float*)d_in[4];
    const float* Wv  = (const float*)d_in[5];
    const float* Wo  = (const float*)d_in[6];
    const float* bo  = (const float*)d_in[7];
    float* out = (float*)d_out;

    __half *xh, *wh;
    float* vsum;
    cudaGetSymbolAddress((void**)&xh, g_x);
    cudaGetSymbolAddress((void**)&wh, g_w);
    cudaGetSymbolAddress((void**)&vsum, g_vsum);

    cudaFuncSetAttribute(qkv_gemm, cudaFuncAttributeMaxDynamicSharedMemorySize, GEMM_SMEM);
    cudaFuncSetAttribute(out_gemm, cudaFuncAttributeMaxDynamicSharedMemorySize, GEMM_SMEM);
    cudaFuncSetAttribute(flash_mma, cudaFuncAttributeMaxDynamicSharedMemorySize, FLASH_SMEM);

    // 0) zero vsum (capture-safe async memset)
    cudaMemsetAsync(vsum, 0, B_ * H_ * DK_ * sizeof(float));

    // 1) convert x to fp16
    convert_kernel<<<(MROWS * D_ / 4) / 256, 256>>>(x, xh);

    // 2) transpose all four weights in one launch
    dim3 tb(32, 8), tg(32, 32, 4);
    transpose_kernel<<<tg, tb>>>(Wq, Wk, Wv, Wo, wh);

    // 3) fused Q/K/V projections + V column sums
    dim3 gq(3 * D_ / 64, MROWS / 128);   // (48, 32)
    qkv_gemm<<<gq, 128, GEMM_SMEM>>>();

    // 4) flash attention (fp16, log2-domain softmax)
    dim3 fg(S_ / 64, B_ * H_);
    flash_mma<<<fg, 128, FLASH_SMEM>>>(kpm);

    // 5) output projection with bias (fp32 out)
    dim3 gg(D_ / 64, MROWS / 128);       // (16, 32)
    out_gemm<<<gg, 128, GEMM_SMEM>>>(bo, out);
}

// round 14
// speedup vs baseline: 2.2697x; 1.0822x over previous
#include <cuda_runtime.h>
#include <cuda_fp16.h>
#include <math.h>
#include <stdint.h>

#define B_  2
#define S_  2048
#define D_  1024
#define H_  16
#define DK_ 64
#define MROWS (B_*S_)      // 4096

// ---------------- scratch (allocation-free: __device__ globals) -------------
__device__ __half g_q[MROWS*D_];
__device__ __half g_k[MROWS*D_];
__device__ __half g_v[MROWS*D_];
__device__ __half g_c[MROWS*D_];           // ctx
__device__ __half g_x[MROWS*D_];
__device__ __half g_w[4*D_*D_];            // W^T [N,K], 4 matrices contiguous
__device__ float g_vsum[B_*H_*DK_];

// ======================= helpers =============================================
__device__ __forceinline__ uint32_t smem_u32(const void* p) {
    uint32_t a;
    asm("{ .reg .u64 t; cvta.to.shared.u64 t, %1; cvt.u32.u64 %0, t; }"
        : "=r"(a) : "l"(p));
    return a;
}
__device__ __forceinline__ void ldsm_x4(uint32_t* r, uint32_t addr) {
    asm volatile("ldmatrix.sync.aligned.m8n8.x4.shared.b16 {%0,%1,%2,%3}, [%4];"
                 : "=r"(r[0]), "=r"(r[1]), "=r"(r[2]), "=r"(r[3]) : "r"(addr));
}
__device__ __forceinline__ void ldsm_x4_t(uint32_t* r, uint32_t addr) {
    asm volatile("ldmatrix.sync.aligned.m8n8.x4.trans.shared.b16 {%0,%1,%2,%3}, [%4];"
                 : "=r"(r[0]), "=r"(r[1]), "=r"(r[2]), "=r"(r[3]) : "r"(addr));
}
__device__ __forceinline__ void mma16816(float* c, const uint32_t* a, const uint32_t* b) {
    asm volatile("mma.sync.aligned.m16n8k16.row.col.f32.f16.f16.f32 "
                 "{%0,%1,%2,%3}, {%4,%5,%6,%7}, {%8,%9}, {%0,%1,%2,%3};"
                 : "+f"(c[0]), "+f"(c[1]), "+f"(c[2]), "+f"(c[3])
                 : "r"(a[0]), "r"(a[1]), "r"(a[2]), "r"(a[3]),
                   "r"(b[0]), "r"(b[1]));
}
__device__ __forceinline__ uint32_t pack_h2(float a, float b) {
    __half2 t = __floats2half2_rn(a, b);
    return *(uint32_t*)&t;
}

// ======================= preprocessing kernels ==============================
__global__ void convert_kernel(const float* __restrict__ src,
                               __half* __restrict__ dst) {
    int i = blockIdx.x * blockDim.x + threadIdx.x;
    float4 v = ((const float4*)src)[i];
    __half2* dp = (__half2*)(dst + 4 * (size_t)i);
    dp[0] = __floats2half2_rn(v.x, v.y);
    dp[1] = __floats2half2_rn(v.z, v.w);
}

__global__ void transpose_kernel(const float* __restrict__ W0,
                                 const float* __restrict__ W1,
                                 const float* __restrict__ W2,
                                 const float* __restrict__ W3,
                                 __half* __restrict__ TB) {
    __shared__ float t[32][33];
    const int z = blockIdx.z;
    const float* W = (z == 0) ? W0 : (z == 1) ? W1 : (z == 2) ? W2 : W3;
    __half* T = TB + (size_t)z * D_ * D_;
    const int n0 = blockIdx.x * 32, k0 = blockIdx.y * 32;
    for (int j = threadIdx.y; j < 32; j += 8)
        t[j][threadIdx.x] = W[(size_t)(k0 + j) * D_ + n0 + threadIdx.x];
    __syncthreads();
    for (int j = threadIdx.y; j < 32; j += 8) {
        float v = t[threadIdx.x][j];
        T[(size_t)(n0 + j) * D_ + k0 + threadIdx.x] = __float2half(v);
    }
}

// ======================= fp16 single GEMM ====================================
#define KC   64
#define SSTR 72
#define SM_A (128 * SSTR)
#define SM_B (64 * SSTR)
#define GEMM_SMEM ((SM_A + SM_B) * 2)    // 27648 B

__device__ __forceinline__ void gemm_mainloop(const __half* __restrict__ A,
                                              const __half* __restrict__ Bp,
                                              __half* smb,
                                              int rowBase, int colBase,
                                              float acc[4][4][4]) {
    __half* As = smb;
    __half* Bs = As + SM_A;

    const int tid  = threadIdx.x;
    const int lane = tid & 31;
    const int wid  = tid >> 5;
    const int wm   = wid >> 1;
    const int wn   = wid & 1;

    const uint32_t sA = smem_u32(As);
    const uint32_t sB = smem_u32(Bs);

    const int r0 = tid >> 3;
    const int cs = (tid & 7) * 8;

    const int aRow = ((lane & 8) ? 8 : 0) + (lane & 7);
    const int aK   = ((lane & 16) ? 8 : 0);
    const int bRow = ((lane & 16) ? 8 : 0) + (lane & 7);
    const int bK   = ((lane & 8) ? 8 : 0);

    for (int c = 0; c < 16; c++) {
        const int kb = c * KC;
        if (c) __syncthreads();
        #pragma unroll
        for (int u = 0; u < 8; u++) {
            const int r = u * 16 + r0;
            const size_t ga = (size_t)(rowBase + r) * D_ + kb + cs;
            *(uint4*)(As + r * SSTR + cs) = *(const uint4*)(A + ga);
        }
        #pragma unroll
        for (int u = 0; u < 4; u++) {
            const int r = u * 16 + r0;
            const size_t gb = (size_t)(colBase + r) * D_ + kb + cs;
            *(uint4*)(Bs + r * SSTR + cs) = *(const uint4*)(Bp + gb);
        }
        __syncthreads();

        #pragma unroll
        for (int k16 = 0; k16 < 4; k16++) {
            const int kk = k16 * 16;
            uint32_t bfr[4][2];
            #pragma unroll
            for (int g = 0; g < 2; g++) {
                const uint32_t off =
                    (uint32_t)((wn * 32 + g * 16 + bRow) * SSTR + kk + bK) * 2;
                uint32_t t4[4];
                ldsm_x4(t4, sB + off);
                bfr[2*g][0] = t4[0]; bfr[2*g][1] = t4[1];
                bfr[2*g+1][0] = t4[2]; bfr[2*g+1][1] = t4[3];
            }
            #pragma unroll
            for (int mi = 0; mi < 4; mi++) {
                const uint32_t offA =
                    (uint32_t)((wm * 64 + mi * 16 + aRow) * SSTR + kk + aK) * 2;
                uint32_t ah[4];
                ldsm_x4(ah, sA + offA);
                #pragma unroll
                for (int ni = 0; ni < 4; ni++)
                    mma16816(acc[mi][ni], ah, bfr[ni]);
            }
        }
    }
}

// fused QKV + fused V-column-sum
__global__ void __launch_bounds__(128) qkv_gemm() {
    extern __shared__ __half smb[];
    const int rowBase = blockIdx.y * 128;
    const int colBase = blockIdx.x * 64;       // [0, 3072)
    const int z = colBase >> 10;               // 0=Q 1=K 2=V
    const int colLoc = colBase & 1023;
    __half* C = (z == 0) ? g_q : (z == 1) ? g_k : g_v;

    float acc[4][4][4];
    #pragma unroll
    for (int i = 0; i < 4; i++)
        #pragma unroll
        for (int j = 0; j < 4; j++)
            #pragma unroll
            for (int q = 0; q < 4; q++) acc[i][j][q] = 0.f;

    gemm_mainloop(g_x, g_w, smb, rowBase, colBase, acc);

    const int lane = threadIdx.x & 31;
    const int wid  = threadIdx.x >> 5;
    const int wm   = wid >> 1;
    const int wn   = wid & 1;
    const int qr = lane >> 2;
    const int qc = (lane & 3) * 2;
    #pragma unroll
    for (int mi = 0; mi < 4; mi++) {
        const int m0 = rowBase + wm * 64 + mi * 16 + qr;
        #pragma unroll
        for (int ni = 0; ni < 4; ni++) {
            const int cc = colLoc + wn * 32 + ni * 8 + qc;
            #pragma unroll
            for (int rr = 0; rr < 2; rr++) {
                const size_t o = (size_t)(m0 + rr * 8) * D_ + cc;
                *(__half2*)(C + o) = __floats2half2_rn(acc[mi][ni][rr*2+0],
                                                       acc[mi][ni][rr*2+1]);
            }
        }
    }

    if (z == 2) {
        const int b = rowBase >> 11;
        const int h = colLoc >> 6;
        #pragma unroll
        for (int ni = 0; ni < 4; ni++) {
            float c0 = 0.f, c1 = 0.f;
            #pragma unroll
            for (int mi = 0; mi < 4; mi++) {
                c0 += acc[mi][ni][0] + acc[mi][ni][2];
                c1 += acc[mi][ni][1] + acc[mi][ni][3];
            }
            c0 += __shfl_xor_sync(0xffffffffu, c0, 4);
            c0 += __shfl_xor_sync(0xffffffffu, c0, 8);
            c0 += __shfl_xor_sync(0xffffffffu, c0, 16);
            c1 += __shfl_xor_sync(0xffffffffu, c1, 4);
            c1 += __shfl_xor_sync(0xffffffffu, c1, 8);
            c1 += __shfl_xor_sync(0xffffffffu, c1, 16);
            if (qr == 0) {
                const int dd = wn * 32 + ni * 8 + qc;
                atomicAdd(&g_vsum[(b * H_ + h) * DK_ + dd], c0);
                atomicAdd(&g_vsum[(b * H_ + h) * DK_ + dd + 1], c1);
            }
        }
    }
}

// output projection with bias, fp32 out
__global__ void __launch_bounds__(128) out_gemm(const float* __restrict__ bias,
                                                float* __restrict__ C) {
    extern __shared__ __half smb[];
    const int rowBase = blockIdx.y * 128;
    const int colBase = blockIdx.x * 64;

    float acc[4][4][4];
    #pragma unroll
    for (int i = 0; i < 4; i++)
        #pragma unroll
        for (int j = 0; j < 4; j++)
            #pragma unroll
            for (int q = 0; q < 4; q++) acc[i][j][q] = 0.f;

    gemm_mainloop(g_c, g_w + 3 * (size_t)D_ * D_, smb, rowBase, colBase, acc);

    const int lane = threadIdx.x & 31;
    const int wid  = threadIdx.x >> 5;
    const int wm   = wid >> 1;
    const int wn   = wid & 1;
    const int qr = lane >> 2;
    const int qc = (lane & 3) * 2;
    #pragma unroll
    for (int mi = 0; mi < 4; mi++) {
        const int m0 = rowBase + wm * 64 + mi * 16 + qr;
        #pragma unroll
        for (int ni = 0; ni < 4; ni++) {
            const int cc = colBase + wn * 32 + ni * 8 + qc;
            float b0 = bias[cc], b1 = bias[cc + 1];
            float2 v0; v0.x = acc[mi][ni][0] + b0; v0.y = acc[mi][ni][1] + b1;
            float2 v1; v1.x = acc[mi][ni][2] + b0; v1.y = acc[mi][ni][3] + b1;
            *(float2*)&C[(size_t)m0 * D_ + cc] = v0;
            *(float2*)&C[(size_t)(m0 + 8) * D_ + cc] = v1;
        }
    }
}

// ================= flash attention: paired q-blocks (uniform 33 tiles/CTA) ===
// scale = 1/8 (score) * log2(e) so probabilities use exp2 directly
#define FSC 0.180336880f
#define FS 72
#define FLASH_SMEM (3 * 64 * FS * 2 + 64 * 4)    // 27904 B

__global__ void __launch_bounds__(128) flash_mma(const int* __restrict__ kpm) {
    extern __shared__ __half fsm[];
    __half* Qs = fsm;
    __half* Ks = Qs + 64 * FS;
    __half* Vs = Ks + 64 * FS;
    float* padf = (float*)(Vs + 64 * FS);

    const int tid  = threadIdx.x;
    const int lane = tid & 31;
    const int wq   = tid >> 5;
    const int pair = blockIdx.x;                // 0..15
    const int bh   = blockIdx.y;
    const int b = bh / H_, h = bh % H_;

    const uint32_t sQ = smem_u32(Qs);
    const uint32_t sK = smem_u32(Ks);
    const uint32_t sV = smem_u32(Vs);

    const size_t headOff = (size_t)b * S_ * D_ + h * DK_;

    const int aRow = ((lane & 8) ? 8 : 0) + (lane & 7);
    const int aK   = ((lane & 16) ? 8 : 0);
    const int bRow = ((lane & 16) ? 8 : 0) + (lane & 7);
    const int bK   = ((lane & 8) ? 8 : 0);
    const int vRow = ((lane & 8) ? 8 : 0) + (lane & 7);
    const int vCol = ((lane & 16) ? 8 : 0);
    const int colq = (lane & 3) * 2;
    const float invS = 1.0f / (float)S_;

    #pragma unroll 1
    for (int hf = 0; hf < 2; hf++) {
        const int qblk = (hf == 0) ? (31 - pair) : pair;   // big half first
        const size_t qOff = headOff + (size_t)(qblk * 64) * D_;

        __syncthreads();                       // protect Qs reuse across halves
        #pragma unroll
        for (int u = 0; u < 4; u++) {
            const int idx = u * 128 + tid;
            const int r = idx >> 3, c = (idx & 7) * 8;
            *(uint4*)(Qs + r * FS + c) = *(const uint4*)(g_q + qOff + (size_t)r * D_ + c);
        }

        float m0 = -INFINITY, m1 = -INFINITY, l0 = 0.f, l1 = 0.f;
        float oacc[8][4];
        #pragma unroll
        for (int ni = 0; ni < 8; ni++)
            #pragma unroll
            for (int q = 0; q < 4; q++) oacc[ni][q] = 0.f;

        const int qr0 = qblk * 64 + wq * 16 + (lane >> 2);
        const int qr1 = qr0 + 8;

        for (int kt = 0; kt <= qblk; kt++) {
            __syncthreads();
            {
                const size_t kOff = headOff + (size_t)(kt * 64) * D_;
                #pragma unroll
                for (int u = 0; u < 4; u++) {
                    const int idx = u * 128 + tid;
                    const int r = idx >> 3, c = (idx & 7) * 8;
                    const size_t go = kOff + (size_t)r * D_ + c;
                    const int so = r * FS + c;
                    *(uint4*)(Ks + so) = *(const uint4*)(g_k + go);
                    *(uint4*)(Vs + so) = *(const uint4*)(g_v + go);
                }
                if (tid < 64) padf[tid] = kpm[b * S_ + kt * 64 + tid] ? -INFINITY : 0.f;
            }
            __syncthreads();

            // ---- S = Q @ K^T ----
            float sacc[8][4];
            #pragma unroll
            for (int ni = 0; ni < 8; ni++)
                #pragma unroll
                for (int q = 0; q < 4; q++) sacc[ni][q] = 0.f;

            #pragma unroll
            for (int j = 0; j < 4; j++) {
                const int kk = j * 16;
                uint32_t ah[4];
                ldsm_x4(ah, sQ + (uint32_t)((wq * 16 + aRow) * FS + kk + aK) * 2);
                #pragma unroll
                for (int g = 0; g < 4; g++) {
                    const uint32_t off = (uint32_t)((g * 16 + bRow) * FS + kk + bK) * 2;
                    uint32_t th[4];
                    ldsm_x4(th, sK + off);
                    mma16816(sacc[2*g],   ah, th);
                    mma16816(sacc[2*g+1], ah, th + 2);
                }
            }

            // ---- scale + padding FMA; causal only on diagonal tile ----
            const bool diag = (kt == qblk);
            #pragma unroll
            for (int ni = 0; ni < 8; ni++) {
                const float pj0 = padf[ni * 8 + colq];
                const float pj1 = padf[ni * 8 + colq + 1];
                sacc[ni][0] = fmaf(sacc[ni][0], FSC, pj0);
                sacc[ni][1] = fmaf(sacc[ni][1], FSC, pj1);
                sacc[ni][2] = fmaf(sacc[ni][2], FSC, pj0);
                sacc[ni][3] = fmaf(sacc[ni][3], FSC, pj1);
                if (diag) {
                    const int kc = kt * 64 + ni * 8 + colq;
                    if (kc     > qr0) sacc[ni][0] = -INFINITY;
                    if (kc + 1 > qr0) sacc[ni][1] = -INFINITY;
                    if (kc     > qr1) sacc[ni][2] = -INFINITY;
                    if (kc + 1 > qr1) sacc[ni][3] = -INFINITY;
                }
            }

            // ---- online softmax (log2 domain) ----
            float mt0 = -INFINITY, mt1 = -INFINITY;
            #pragma unroll
            for (int ni = 0; ni < 8; ni++) {
                mt0 = fmaxf(mt0, fmaxf(sacc[ni][0], sacc[ni][1]));
                mt1 = fmaxf(mt1, fmaxf(sacc[ni][2], sacc[ni][3]));
            }
            mt0 = fmaxf(mt0, __shfl_xor_sync(0xffffffffu, mt0, 1));
            mt0 = fmaxf(mt0, __shfl_xor_sync(0xffffffffu, mt0, 2));
            mt1 = fmaxf(mt1, __shfl_xor_sync(0xffffffffu, mt1, 1));
            mt1 = fmaxf(mt1, __shfl_xor_sync(0xffffffffu, mt1, 2));

            const float mn0 = fmaxf(m0, mt0);
            const float mn1 = fmaxf(m1, mt1);
            const bool live0 = (mn0 != -INFINITY);
            const bool live1 = (mn1 != -INFINITY);
            const float alpha0 = live0 ? exp2f(m0 - mn0) : 1.f;
            const float alpha1 = live1 ? exp2f(m1 - mn1) : 1.f;

            float ps0 = 0.f, ps1 = 0.f;
            #pragma unroll
            for (int ni = 0; ni < 8; ni++) {
                float p00 = live0 ? exp2f(sacc[ni][0] - mn0) : 0.f;
                float p01 = live0 ? exp2f(sacc[ni][1] - mn0) : 0.f;
                float p10 = live1 ? exp2f(sacc[ni][2] - mn1) : 0.f;
                float p11 = live1 ? exp2f(sacc[ni][3] - mn1) : 0.f;
                sacc[ni][0] = p00; sacc[ni][1] = p01;
                sacc[ni][2] = p10; sacc[ni][3] = p11;
                ps0 += p00 + p01;
                ps1 += p10 + p11;
            }
            ps0 += __shfl_xor_sync(0xffffffffu, ps0, 1);
            ps0 += __shfl_xor_sync(0xffffffffu, ps0, 2);
            ps1 += __shfl_xor_sync(0xffffffffu, ps1, 1);
            ps1 += __shfl_xor_sync(0xffffffffu, ps1, 2);

            l0 = l0 * alpha0 + ps0;
            l1 = l1 * alpha1 + ps1;
            m0 = mn0; m1 = mn1;
            #pragma unroll
            for (int ni = 0; ni < 8; ni++) {
                oacc[ni][0] *= alpha0; oacc[ni][1] *= alpha0;
                oacc[ni][2] *= alpha1; oacc[ni][3] *= alpha1;
            }

            // ---- O += P @ V ----
            #pragma unroll
            for (int j = 0; j < 4; j++) {
                uint32_t af[4];
                #pragma unroll
                for (int t = 0; t < 2; t++) {
                    af[2*t]   = pack_h2(sacc[2*j+t][0], sacc[2*j+t][1]);
                    af[2*t+1] = pack_h2(sacc[2*j+t][2], sacc[2*j+t][3]);
                }
                #pragma unroll
                for (int g = 0; g < 4; g++) {
                    const uint32_t off =
                        (uint32_t)((j * 16 + vRow) * FS + g * 16 + vCol) * 2;
                    uint32_t vb[4];
                    ldsm_x4_t(vb, sV + off);
                    mma16816(oacc[2*g],   af, vb);
                    mma16816(oacc[2*g+1], af, vb + 2);
                }
            }
        }

        // ---- epilogue ----
        const bool dead0 = (m0 == -INFINITY);
        const bool dead1 = (m1 == -INFINITY);
        const float inv0 = dead0 ? 0.f : 1.0f / l0;
        const float inv1 = dead1 ? 0.f : 1.0f / l1;
        const size_t row0 = (size_t)b * S_ + qr0;
        const size_t row1 = (size_t)b * S_ + qr1;
        #pragma unroll
        for (int ni = 0; ni < 8; ni++) {
            const int dd = ni * 8 + colq;
            float v00, v01, v10, v11;
            if (dead0) {
                v00 = g_vsum[bh * DK_ + dd] * invS;
                v01 = g_vsum[bh * DK_ + dd + 1] * invS;
            } else { v00 = oacc[ni][0] * inv0; v01 = oacc[ni][1] * inv0; }
            if (dead1) {
                v10 = g_vsum[bh * DK_ + dd] * invS;
                v11 = g_vsum[bh * DK_ + dd + 1] * invS;
            } else { v10 = oacc[ni][2] * inv1; v11 = oacc[ni][3] * inv1; }

            const size_t o0 = row0 * D_ + h * DK_ + dd;
            const size_t o1 = row1 * D_ + h * DK_ + dd;
            *(__half2*)(g_c + o0) = __floats2half2_rn(v00, v01);
            *(__half2*)(g_c + o1) = __floats2half2_rn(v10, v11);
        }
    }
}

// ---------------- launch ------------------------------------------------------
extern "C" void kernel_launch(void* const* d_in, const int* in_sizes, int n_in,
                              void* d_out, int out_size) {
    const float* x   = (const float*)d_in[0];
    const int*   kpm = (const int*)d_in[2];
    const float* Wq  = (const float*)d_in[3];
    const float* Wk  = (const float*)d_in[4];
    const float* Wv  = (const float*)d_in[5];
    const float* Wo  = (const float*)d_in[6];
    const float* bo  = (const float*)d_in[7];
    float* out = (float*)d_out;

    __half *xh, *wh;
    float* vsum;
    cudaGetSymbolAddress((void**)&xh, g_x);
    cudaGetSymbolAddress((void**)&wh, g_w);
    cudaGetSymbolAddress((void**)&vsum, g_vsum);

    cudaFuncSetAttribute(qkv_gemm, cudaFuncAttributeMaxDynamicSharedMemorySize, GEMM_SMEM);
    cudaFuncSetAttribute(out_gemm, cudaFuncAttributeMaxDynamicSharedMemorySize, GEMM_SMEM);
    cudaFuncSetAttribute(flash_mma, cudaFuncAttributeMaxDynamicSharedMemorySize, FLASH_SMEM);

    // 0) zero vsum (capture-safe async memset)
    cudaMemsetAsync(vsum, 0, B_ * H_ * DK_ * sizeof(float));

    // 1) convert x to fp16
    convert_kernel<<<(MROWS * D_ / 4) / 256, 256>>>(x, xh);

    // 2) transpose all four weights in one launch
    dim3 tb(32, 8), tg(32, 32, 4);
    transpose_kernel<<<tg, tb>>>(Wq, Wk, Wv, Wo, wh);

    // 3) fused Q/K/V projections + V column sums
    dim3 gq(3 * D_ / 64, MROWS / 128);   // (48, 32)
    qkv_gemm<<<gq, 128, GEMM_SMEM>>>();

    // 4) flash attention: paired q-blocks, uniform 33 tiles per CTA
    dim3 fg(S_ / 128, B_ * H_);          // (16, 32)
    flash_mma<<<fg, 128, FLASH_SMEM>>>(kpm);

    // 5) output projection with bias (fp32 out)
    dim3 gg(D_ / 64, MROWS / 128);       // (16, 32)
    out_gemm<<<gg, 128, GEMM_SMEM>>>(bo, out);
}

// round 15
// speedup vs baseline: 2.3378x; 1.0300x over previous
#include <cuda_runtime.h>
#include <cuda_fp16.h>
#include <math.h>
#include <stdint.h>

#define B_  2
#define S_  2048
#define D_  1024
#define H_  16
#define DK_ 64
#define MROWS (B_*S_)      // 4096

// ---------------- scratch (allocation-free: __device__ globals) -------------
__device__ __half g_q[MROWS*D_];
__device__ __half g_k[MROWS*D_];
__device__ __half g_v[MROWS*D_];
__device__ __half g_c[MROWS*D_];           // ctx
__device__ __half g_x[MROWS*D_];
__device__ __half g_w[4*D_*D_];            // W^T [N,K], 4 matrices contiguous
__device__ float g_vsum[B_*H_*DK_];

// ======================= helpers =============================================
__device__ __forceinline__ uint32_t smem_u32(const void* p) {
    uint32_t a;
    asm("{ .reg .u64 t; cvta.to.shared.u64 t, %1; cvt.u32.u64 %0, t; }"
        : "=r"(a) : "l"(p));
    return a;
}
__device__ __forceinline__ void ldsm_x4(uint32_t* r, uint32_t addr) {
    asm volatile("ldmatrix.sync.aligned.m8n8.x4.shared.b16 {%0,%1,%2,%3}, [%4];"
                 : "=r"(r[0]), "=r"(r[1]), "=r"(r[2]), "=r"(r[3]) : "r"(addr));
}
__device__ __forceinline__ void ldsm_x4_t(uint32_t* r, uint32_t addr) {
    asm volatile("ldmatrix.sync.aligned.m8n8.x4.trans.shared.b16 {%0,%1,%2,%3}, [%4];"
                 : "=r"(r[0]), "=r"(r[1]), "=r"(r[2]), "=r"(r[3]) : "r"(addr));
}
__device__ __forceinline__ void mma16816(float* c, const uint32_t* a, const uint32_t* b) {
    asm volatile("mma.sync.aligned.m16n8k16.row.col.f32.f16.f16.f32 "
                 "{%0,%1,%2,%3}, {%4,%5,%6,%7}, {%8,%9}, {%0,%1,%2,%3};"
                 : "+f"(c[0]), "+f"(c[1]), "+f"(c[2]), "+f"(c[3])
                 : "r"(a[0]), "r"(a[1]), "r"(a[2]), "r"(a[3]),
                   "r"(b[0]), "r"(b[1]));
}
__device__ __forceinline__ uint32_t pack_h2(float a, float b) {
    __half2 t = __floats2half2_rn(a, b);
    return *(uint32_t*)&t;
}
#define CP16(dst, src) \
    asm volatile("cp.async.cg.shared.global [%0], [%1], 16;" \
                 :: "r"((uint32_t)(dst)), "l"(src))
#define CP_COMMIT() asm volatile("cp.async.commit_group;" ::: "memory")
#define CP_WAIT0()  asm volatile("cp.async.wait_group 0;" ::: "memory")

// ======================= preprocessing kernels ==============================
__global__ void convert_kernel(const float* __restrict__ src,
                               __half* __restrict__ dst) {
    int i = blockIdx.x * blockDim.x + threadIdx.x;
    float4 v = ((const float4*)src)[i];
    __half2* dp = (__half2*)(dst + 4 * (size_t)i);
    dp[0] = __floats2half2_rn(v.x, v.y);
    dp[1] = __floats2half2_rn(v.z, v.w);
}

__global__ void transpose_kernel(const float* __restrict__ W0,
                                 const float* __restrict__ W1,
                                 const float* __restrict__ W2,
                                 const float* __restrict__ W3,
                                 __half* __restrict__ TB) {
    __shared__ float t[32][33];
    const int z = blockIdx.z;
    const float* W = (z == 0) ? W0 : (z == 1) ? W1 : (z == 2) ? W2 : W3;
    __half* T = TB + (size_t)z * D_ * D_;
    const int n0 = blockIdx.x * 32, k0 = blockIdx.y * 32;
    for (int j = threadIdx.y; j < 32; j += 8)
        t[j][threadIdx.x] = W[(size_t)(k0 + j) * D_ + n0 + threadIdx.x];
    __syncthreads();
    for (int j = threadIdx.y; j < 32; j += 8) {
        float v = t[threadIdx.x][j];
        T[(size_t)(n0 + j) * D_ + k0 + threadIdx.x] = __float2half(v);
    }
}

// ======================= fp16 single GEMM ====================================
#define KC   64
#define SSTR 72
#define SM_A (128 * SSTR)
#define SM_B (64 * SSTR)
#define GEMM_SMEM ((SM_A + SM_B) * 2)    // 27648 B

__device__ __forceinline__ void gemm_mainloop(const __half* __restrict__ A,
                                              const __half* __restrict__ Bp,
                                              __half* smb,
                                              int rowBase, int colBase,
                                              float acc[4][4][4]) {
    __half* As = smb;
    __half* Bs = As + SM_A;

    const int tid  = threadIdx.x;
    const int lane = tid & 31;
    const int wid  = tid >> 5;
    const int wm   = wid >> 1;
    const int wn   = wid & 1;

    const uint32_t sA = smem_u32(As);
    const uint32_t sB = smem_u32(Bs);

    const int r0 = tid >> 3;
    const int cs = (tid & 7) * 8;

    const int aRow = ((lane & 8) ? 8 : 0) + (lane & 7);
    const int aK   = ((lane & 16) ? 8 : 0);
    const int bRow = ((lane & 16) ? 8 : 0) + (lane & 7);
    const int bK   = ((lane & 8) ? 8 : 0);

    for (int c = 0; c < 16; c++) {
        const int kb = c * KC;
        if (c) __syncthreads();
        #pragma unroll
        for (int u = 0; u < 8; u++) {
            const int r = u * 16 + r0;
            const size_t ga = (size_t)(rowBase + r) * D_ + kb + cs;
            *(uint4*)(As + r * SSTR + cs) = *(const uint4*)(A + ga);
        }
        #pragma unroll
        for (int u = 0; u < 4; u++) {
            const int r = u * 16 + r0;
            const size_t gb = (size_t)(colBase + r) * D_ + kb + cs;
            *(uint4*)(Bs + r * SSTR + cs) = *(const uint4*)(Bp + gb);
        }
        __syncthreads();

        #pragma unroll
        for (int k16 = 0; k16 < 4; k16++) {
            const int kk = k16 * 16;
            uint32_t bfr[4][2];
            #pragma unroll
            for (int g = 0; g < 2; g++) {
                const uint32_t off =
                    (uint32_t)((wn * 32 + g * 16 + bRow) * SSTR + kk + bK) * 2;
                uint32_t t4[4];
                ldsm_x4(t4, sB + off);
                bfr[2*g][0] = t4[0]; bfr[2*g][1] = t4[1];
                bfr[2*g+1][0] = t4[2]; bfr[2*g+1][1] = t4[3];
            }
            #pragma unroll
            for (int mi = 0; mi < 4; mi++) {
                const uint32_t offA =
                    (uint32_t)((wm * 64 + mi * 16 + aRow) * SSTR + kk + aK) * 2;
                uint32_t ah[4];
                ldsm_x4(ah, sA + offA);
                #pragma unroll
                for (int ni = 0; ni < 4; ni++)
                    mma16816(acc[mi][ni], ah, bfr[ni]);
            }
        }
    }
}

// fused QKV + fused V-column-sum
__global__ void __launch_bounds__(128) qkv_gemm() {
    extern __shared__ __half smb[];
    const int rowBase = blockIdx.y * 128;
    const int colBase = blockIdx.x * 64;       // [0, 3072)
    const int z = colBase >> 10;               // 0=Q 1=K 2=V
    const int colLoc = colBase & 1023;
    __half* C = (z == 0) ? g_q : (z == 1) ? g_k : g_v;

    float acc[4][4][4];
    #pragma unroll
    for (int i = 0; i < 4; i++)
        #pragma unroll
        for (int j = 0; j < 4; j++)
            #pragma unroll
            for (int q = 0; q < 4; q++) acc[i][j][q] = 0.f;

    gemm_mainloop(g_x, g_w, smb, rowBase, colBase, acc);

    const int lane = threadIdx.x & 31;
    const int wid  = threadIdx.x >> 5;
    const int wm   = wid >> 1;
    const int wn   = wid & 1;
    const int qr = lane >> 2;
    const int qc = (lane & 3) * 2;
    #pragma unroll
    for (int mi = 0; mi < 4; mi++) {
        const int m0 = rowBase + wm * 64 + mi * 16 + qr;
        #pragma unroll
        for (int ni = 0; ni < 4; ni++) {
            const int cc = colLoc + wn * 32 + ni * 8 + qc;
            #pragma unroll
            for (int rr = 0; rr < 2; rr++) {
                const size_t o = (size_t)(m0 + rr * 8) * D_ + cc;
                *(__half2*)(C + o) = __floats2half2_rn(acc[mi][ni][rr*2+0],
                                                       acc[mi][ni][rr*2+1]);
            }
        }
    }

    if (z == 2) {
        const int b = rowBase >> 11;
        const int h = colLoc >> 6;
        #pragma unroll
        for (int ni = 0; ni < 4; ni++) {
            float c0 = 0.f, c1 = 0.f;
            #pragma unroll
            for (int mi = 0; mi < 4; mi++) {
                c0 += acc[mi][ni][0] + acc[mi][ni][2];
                c1 += acc[mi][ni][1] + acc[mi][ni][3];
            }
            c0 += __shfl_xor_sync(0xffffffffu, c0, 4);
            c0 += __shfl_xor_sync(0xffffffffu, c0, 8);
            c0 += __shfl_xor_sync(0xffffffffu, c0, 16);
            c1 += __shfl_xor_sync(0xffffffffu, c1, 4);
            c1 += __shfl_xor_sync(0xffffffffu, c1, 8);
            c1 += __shfl_xor_sync(0xffffffffu, c1, 16);
            if (qr == 0) {
                const int dd = wn * 32 + ni * 8 + qc;
                atomicAdd(&g_vsum[(b * H_ + h) * DK_ + dd], c0);
                atomicAdd(&g_vsum[(b * H_ + h) * DK_ + dd + 1], c1);
            }
        }
    }
}

// output projection with bias, fp32 out
__global__ void __launch_bounds__(128) out_gemm(const float* __restrict__ bias,
                                                float* __restrict__ C) {
    extern __shared__ __half smb[];
    const int rowBase = blockIdx.y * 128;
    const int colBase = blockIdx.x * 64;

    float acc[4][4][4];
    #pragma unroll
    for (int i = 0; i < 4; i++)
        #pragma unroll
        for (int j = 0; j < 4; j++)
            #pragma unroll
            for (int q = 0; q < 4; q++) acc[i][j][q] = 0.f;

    gemm_mainloop(g_c, g_w + 3 * (size_t)D_ * D_, smb, rowBase, colBase, acc);

    const int lane = threadIdx.x & 31;
    const int wid  = threadIdx.x >> 5;
    const int wm   = wid >> 1;
    const int wn   = wid & 1;
    const int qr = lane >> 2;
    const int qc = (lane & 3) * 2;
    #pragma unroll
    for (int mi = 0; mi < 4; mi++) {
        const int m0 = rowBase + wm * 64 + mi * 16 + qr;
        #pragma unroll
        for (int ni = 0; ni < 4; ni++) {
            const int cc = colBase + wn * 32 + ni * 8 + qc;
            float b0 = bias[cc], b1 = bias[cc + 1];
            float2 v0; v0.x = acc[mi][ni][0] + b0; v0.y = acc[mi][ni][1] + b1;
            float2 v1; v1.x = acc[mi][ni][2] + b0; v1.y = acc[mi][ni][3] + b1;
            *(float2*)&C[(size_t)m0 * D_ + cc] = v0;
            *(float2*)&C[(size_t)(m0 + 8) * D_ + cc] = v1;
        }
    }
}

// ======== flash attention: paired q-blocks + cp.async double-buffered K/V ====
#define FSC 0.180336880f
#define FS 72
#define F_T (64 * FS)                            // elems per 64x64 tile
#define FLASH_SMEM (5 * F_T * 2 + 2 * 64 * 4)    // Q + 2 KV stages + padf[2][64]

__global__ void __launch_bounds__(128) flash_mma(const int* __restrict__ kpm) {
    extern __shared__ __half fsm[];
    __half* Qs = fsm;
    // stage s: K at Qs + F_T + s*2*F_T, V = K + F_T
    float* padf = (float*)(fsm + 5 * F_T);       // [2][64]

    const int tid  = threadIdx.x;
    const int lane = tid & 31;
    const int wq   = tid >> 5;
    const int pair = blockIdx.x;                // 0..15
    const int bh   = blockIdx.y;
    const int b = bh / H_, h = bh % H_;

    const uint32_t sQ   = smem_u32(Qs);
    const uint32_t sKV0 = sQ + F_T * 2;          // bytes
    const size_t headOff = (size_t)b * S_ * D_ + h * DK_;

    const int aRow = ((lane & 8) ? 8 : 0) + (lane & 7);
    const int aK   = ((lane & 16) ? 8 : 0);
    const int bRow = ((lane & 16) ? 8 : 0) + (lane & 7);
    const int bK   = ((lane & 8) ? 8 : 0);
    const int vRow = ((lane & 8) ? 8 : 0) + (lane & 7);
    const int vCol = ((lane & 16) ? 8 : 0);
    const int colq = (lane & 3) * 2;
    const float invS = 1.0f / (float)S_;

    // copy geometry: per thread 4 rows (K) + 4 rows (V) of 16B
    const int fr = tid >> 3;                    // 0..15
    const int fc = (tid & 7) * 8;
    const uint32_t fdst = (uint32_t)(fr * FS + fc) * 2;

    #pragma unroll 1
    for (int hf = 0; hf < 2; hf++) {
        const int qblk = (hf == 0) ? (31 - pair) : pair;   // big half first
        const size_t qOff = headOff + (size_t)(qblk * 64) * D_;

        __syncthreads();                        // prior half done with all smem
        // issue Q + stage0 K/V + padf0
        #pragma unroll
        for (int u = 0; u < 4; u++) {
            const uint32_t d = fdst + (uint32_t)(u * 16 * FS) * 2;
            const size_t gq = qOff + (size_t)(fr + u * 16) * D_ + fc;
            CP16(sQ + d, g_q + gq);
            const size_t gk = headOff + (size_t)(fr + u * 16) * D_ + fc;  // kt=0
            CP16(sKV0 + d, g_k + gk);
            CP16(sKV0 + F_T * 2 + d, g_v + gk);
        }
        if (tid < 64) padf[tid] = kpm[b * S_ + tid] ? -INFINITY : 0.f;
        CP_COMMIT();

        float m0 = -INFINITY, m1 = -INFINITY, l0 = 0.f, l1 = 0.f;
        float oacc[8][4];
        #pragma unroll
        for (int ni = 0; ni < 8; ni++)
            #pragma unroll
            for (int q = 0; q < 4; q++) oacc[ni][q] = 0.f;

        const int qr0 = qblk * 64 + wq * 16 + (lane >> 2);
        const int qr1 = qr0 + 8;

        for (int kt = 0; kt <= qblk; kt++) {
            CP_WAIT0();
            __syncthreads();

            // issue next stage during this tile's compute
            if (kt + 1 <= qblk) {
                const uint32_t st = sKV0 + ((kt + 1) & 1) * (2 * F_T * 2);
                const size_t kOff = headOff + (size_t)((kt + 1) * 64) * D_;
                #pragma unroll
                for (int u = 0; u < 4; u++) {
                    const uint32_t d = fdst + (uint32_t)(u * 16 * FS) * 2;
                    const size_t gk = kOff + (size_t)(fr + u * 16) * D_ + fc;
                    CP16(st + d, g_k + gk);
                    CP16(st + F_T * 2 + d, g_v + gk);
                }
                if (tid < 64)
                    padf[((kt + 1) & 1) * 64 + tid] =
                        kpm[b * S_ + (kt + 1) * 64 + tid] ? -INFINITY : 0.f;
                CP_COMMIT();
            }

            const uint32_t sK = sKV0 + (kt & 1) * (2 * F_T * 2);
            const uint32_t sV = sK + F_T * 2;
            const float* pd = padf + (kt & 1) * 64;

            // ---- S = Q @ K^T ----
            float sacc[8][4];
            #pragma unroll
            for (int ni = 0; ni < 8; ni++)
                #pragma unroll
                for (int q = 0; q < 4; q++) sacc[ni][q] = 0.f;

            #pragma unroll
            for (int j = 0; j < 4; j++) {
                const int kk = j * 16;
                uint32_t ah[4];
                ldsm_x4(ah, sQ + (uint32_t)((wq * 16 + aRow) * FS + kk + aK) * 2);
                #pragma unroll
                for (int g = 0; g < 4; g++) {
                    const uint32_t off = (uint32_t)((g * 16 + bRow) * FS + kk + bK) * 2;
                    uint32_t th[4];
                    ldsm_x4(th, sK + off);
                    mma16816(sacc[2*g],   ah, th);
                    mma16816(sacc[2*g+1], ah, th + 2);
                }
            }

            // ---- scale + padding FMA; causal only on diagonal tile ----
            const bool diag = (kt == qblk);
            #pragma unroll
            for (int ni = 0; ni < 8; ni++) {
                const float pj0 = pd[ni * 8 + colq];
                const float pj1 = pd[ni * 8 + colq + 1];
                sacc[ni][0] = fmaf(sacc[ni][0], FSC, pj0);
                sacc[ni][1] = fmaf(sacc[ni][1], FSC, pj1);
                sacc[ni][2] = fmaf(sacc[ni][2], FSC, pj0);
                sacc[ni][3] = fmaf(sacc[ni][3], FSC, pj1);
                if (diag) {
                    const int kc = kt * 64 + ni * 8 + colq;
                    if (kc     > qr0) sacc[ni][0] = -INFINITY;
                    if (kc + 1 > qr0) sacc[ni][1] = -INFINITY;
                    if (kc     > qr1) sacc[ni][2] = -INFINITY;
                    if (kc + 1 > qr1) sacc[ni][3] = -INFINITY;
                }
            }

            // ---- online softmax (log2 domain) ----
            float mt0 = -INFINITY, mt1 = -INFINITY;
            #pragma unroll
            for (int ni = 0; ni < 8; ni++) {
                mt0 = fmaxf(mt0, fmaxf(sacc[ni][0], sacc[ni][1]));
                mt1 = fmaxf(mt1, fmaxf(sacc[ni][2], sacc[ni][3]));
            }
            mt0 = fmaxf(mt0, __shfl_xor_sync(0xffffffffu, mt0, 1));
            mt0 = fmaxf(mt0, __shfl_xor_sync(0xffffffffu, mt0, 2));
            mt1 = fmaxf(mt1, __shfl_xor_sync(0xffffffffu, mt1, 1));
            mt1 = fmaxf(mt1, __shfl_xor_sync(0xffffffffu, mt1, 2));

            const float mn0 = fmaxf(m0, mt0);
            const float mn1 = fmaxf(m1, mt1);
            const bool live0 = (mn0 != -INFINITY);
            const bool live1 = (mn1 != -INFINITY);
            const float alpha0 = live0 ? exp2f(m0 - mn0) : 1.f;
            const float alpha1 = live1 ? exp2f(m1 - mn1) : 1.f;

            float ps0 = 0.f, ps1 = 0.f;
            #pragma unroll
            for (int ni = 0; ni < 8; ni++) {
                float p00 = live0 ? exp2f(sacc[ni][0] - mn0) : 0.f;
                float p01 = live0 ? exp2f(sacc[ni][1] - mn0) : 0.f;
                float p10 = live1 ? exp2f(sacc[ni][2] - mn1) : 0.f;
                float p11 = live1 ? exp2f(sacc[ni][3] - mn1) : 0.f;
                sacc[ni][0] = p00; sacc[ni][1] = p01;
                sacc[ni][2] = p10; sacc[ni][3] = p11;
                ps0 += p00 + p01;
                ps1 += p10 + p11;
            }
            ps0 += __shfl_xor_sync(0xffffffffu, ps0, 1);
            ps0 += __shfl_xor_sync(0xffffffffu, ps0, 2);
            ps1 += __shfl_xor_sync(0xffffffffu, ps1, 1);
            ps1 += __shfl_xor_sync(0xffffffffu, ps1, 2);

            l0 = l0 * alpha0 + ps0;
            l1 = l1 * alpha1 + ps1;
            m0 = mn0; m1 = mn1;
            #pragma unroll
            for (int ni = 0; ni < 8; ni++) {
                oacc[ni][0] *= alpha0; oacc[ni][1] *= alpha0;
                oacc[ni][2] *= alpha1; oacc[ni][3] *= alpha1;
            }

            // ---- O += P @ V ----
            #pragma unroll
            for (int j = 0; j < 4; j++) {
                uint32_t af[4];
                #pragma unroll
                for (int t = 0; t < 2; t++) {
                    af[2*t]   = pack_h2(sacc[2*j+t][0], sacc[2*j+t][1]);
                    af[2*t+1] = pack_h2(sacc[2*j+t][2], sacc[2*j+t][3]);
                }
                #pragma unroll
                for (int g = 0; g < 4; g++) {
                    const uint32_t off =
                        (uint32_t)((j * 16 + vRow) * FS + g * 16 + vCol) * 2;
                    uint32_t vb[4];
                    ldsm_x4_t(vb, sV + off);
                    mma16816(oacc[2*g],   af, vb);
                    mma16816(oacc[2*g+1], af, vb + 2);
                }
            }
        }

        // ---- epilogue ----
        const bool dead0 = (m0 == -INFINITY);
        const bool dead1 = (m1 == -INFINITY);
        const float inv0 = dead0 ? 0.f : 1.0f / l0;
        const float inv1 = dead1 ? 0.f : 1.0f / l1;
        const size_t row0 = (size_t)b * S_ + qr0;
        const size_t row1 = (size_t)b * S_ + qr1;
        #pragma unroll
        for (int ni = 0; ni < 8; ni++) {
            const int dd = ni * 8 + colq;
            float v00, v01, v10, v11;
            if (dead0) {
                v00 = g_vsum[bh * DK_ + dd] * invS;
                v01 = g_vsum[bh * DK_ + dd + 1] * invS;
            } else { v00 = oacc[ni][0] * inv0; v01 = oacc[ni][1] * inv0; }
            if (dead1) {
                v10 = g_vsum[bh * DK_ + dd] * invS;
                v11 = g_vsum[bh * DK_ + dd + 1] * invS;
            } else { v10 = oacc[ni][2] * inv1; v11 = oacc[ni][3] * inv1; }

            const size_t o0 = row0 * D_ + h * DK_ + dd;
            const size_t o1 = row1 * D_ + h * DK_ + dd;
            *(__half2*)(g_c + o0) = __floats2half2_rn(v00, v01);
            *(__half2*)(g_c + o1) = __floats2half2_rn(v10, v11);
        }
    }
}

// ---------------- launch ------------------------------------------------------
extern "C" void kernel_launch(void* const* d_in, const int* in_sizes, int n_in,
                              void* d_out, int out_size) {
    const float* x   = (const float*)d_in[0];
    const int*   kpm = (const int*)d_in[2];
    const float* Wq  = (const float*)d_in[3];
    const float* Wk  = (const float*)d_in[4];
    const float* Wv  = (const float*)d_in[5];
    const float* Wo  = (const float*)d_in[6];
    const float* bo  = (const float*)d_in[7];
    float* out = (float*)d_out;

    __half *xh, *wh;
    float* vsum;
    cudaGetSymbolAddress((void**)&xh, g_x);
    cudaGetSymbolAddress((void**)&wh, g_w);
    cudaGetSymbolAddress((void**)&vsum, g_vsum);

    cudaFuncSetAttribute(qkv_gemm, cudaFuncAttributeMaxDynamicSharedMemorySize, GEMM_SMEM);
    cudaFuncSetAttribute(out_gemm, cudaFuncAttributeMaxDynamicSharedMemorySize, GEMM_SMEM);
    cudaFuncSetAttribute(flash_mma, cudaFuncAttributeMaxDynamicSharedMemorySize, FLASH_SMEM);

    // 0) zero vsum (capture-safe async memset)
    cudaMemsetAsync(vsum, 0, B_ * H_ * DK_ * sizeof(float));

    // 1) convert x to fp16
    convert_kernel<<<(MROWS * D_ / 4) / 256, 256>>>(x, xh);

    // 2) transpose all four weights in one launch
    dim3 tb(32, 8), tg(32, 32, 4);
    transpose_kernel<<<tg, tb>>>(Wq, Wk, Wv, Wo, wh);

    // 3) fused Q/K/V projections + V column sums
    dim3 gq(3 * D_ / 64, MROWS / 128);   // (48, 32)
    qkv_gemm<<<gq, 128, GEMM_SMEM>>>();

    // 4) flash attention: paired q-blocks + double-buffered K/V
    dim3 fg(S_ / 128, B_ * H_);          // (16, 32)
    flash_mma<<<fg, 128, FLASH_SMEM>>>(kpm);

    // 5) output projection with bias (fp32 out)
    dim3 gg(D_ / 64, MROWS / 128);       // (16, 32)
    out_gemm<<<gg, 128, GEMM_SMEM>>>(bo, out);
}

// round 16
// speedup vs baseline: 2.5798x; 1.1035x over previous
#include <cuda_runtime.h>
#include <cuda_fp16.h>
#include <math.h>
#include <stdint.h>

#define B_  2
#define S_  2048
#define D_  1024
#define H_  16
#define DK_ 64
#define MROWS (B_*S_)      // 4096

// ---------------- scratch (allocation-free: __device__ globals) -------------
__device__ __half g_q[MROWS*D_];
__device__ __half g_k[MROWS*D_];
__device__ __half g_v[MROWS*D_];
__device__ __half g_c[MROWS*D_];           // ctx
__device__ __half g_x[MROWS*D_];
__device__ __half g_w[4*D_*D_];            // W^T [N,K], 4 matrices contiguous
__device__ float g_vsum[B_*H_*DK_];

// ======================= helpers =============================================
__device__ __forceinline__ uint32_t smem_u32(const void* p) {
    uint32_t a;
    asm("{ .reg .u64 t; cvta.to.shared.u64 t, %1; cvt.u32.u64 %0, t; }"
        : "=r"(a) : "l"(p));
    return a;
}
__device__ __forceinline__ void ldsm_x4(uint32_t* r, uint32_t addr) {
    asm volatile("ldmatrix.sync.aligned.m8n8.x4.shared.b16 {%0,%1,%2,%3}, [%4];"
                 : "=r"(r[0]), "=r"(r[1]), "=r"(r[2]), "=r"(r[3]) : "r"(addr));
}
__device__ __forceinline__ void ldsm_x4_t(uint32_t* r, uint32_t addr) {
    asm volatile("ldmatrix.sync.aligned.m8n8.x4.trans.shared.b16 {%0,%1,%2,%3}, [%4];"
                 : "=r"(r[0]), "=r"(r[1]), "=r"(r[2]), "=r"(r[3]) : "r"(addr));
}
__device__ __forceinline__ void mma16816(float* c, const uint32_t* a, const uint32_t* b) {
    asm volatile("mma.sync.aligned.m16n8k16.row.col.f32.f16.f16.f32 "
                 "{%0,%1,%2,%3}, {%4,%5,%6,%7}, {%8,%9}, {%0,%1,%2,%3};"
                 : "+f"(c[0]), "+f"(c[1]), "+f"(c[2]), "+f"(c[3])
                 : "r"(a[0]), "r"(a[1]), "r"(a[2]), "r"(a[3]),
                   "r"(b[0]), "r"(b[1]));
}
__device__ __forceinline__ uint32_t pack_h2(float a, float b) {
    __half2 t = __floats2half2_rn(a, b);
    return *(uint32_t*)&t;
}
#define CP16(dst, src) \
    asm volatile("cp.async.cg.shared.global [%0], [%1], 16;" \
                 :: "r"((uint32_t)(dst)), "l"(src))
#define CP_COMMIT() asm volatile("cp.async.commit_group;" ::: "memory")
#define CP_WAIT0()  asm volatile("cp.async.wait_group 0;" ::: "memory")

// ======================= preprocessing kernels ==============================
__global__ void convert_kernel(const float* __restrict__ src,
                               __half* __restrict__ dst) {
    int i = blockIdx.x * blockDim.x + threadIdx.x;
    float4 v = ((const float4*)src)[i];
    __half2* dp = (__half2*)(dst + 4 * (size_t)i);
    dp[0] = __floats2half2_rn(v.x, v.y);
    dp[1] = __floats2half2_rn(v.z, v.w);
}

__global__ void transpose_kernel(const float* __restrict__ W0,
                                 const float* __restrict__ W1,
                                 const float* __restrict__ W2,
                                 const float* __restrict__ W3,
                                 __half* __restrict__ TB) {
    __shared__ float t[32][33];
    const int z = blockIdx.z;
    const float* W = (z == 0) ? W0 : (z == 1) ? W1 : (z == 2) ? W2 : W3;
    __half* T = TB + (size_t)z * D_ * D_;
    const int n0 = blockIdx.x * 32, k0 = blockIdx.y * 32;
    for (int j = threadIdx.y; j < 32; j += 8)
        t[j][threadIdx.x] = W[(size_t)(k0 + j) * D_ + n0 + threadIdx.x];
    __syncthreads();
    for (int j = threadIdx.y; j < 32; j += 8) {
        float v = t[threadIdx.x][j];
        T[(size_t)(n0 + j) * D_ + k0 + threadIdx.x] = __float2half(v);
    }
}

// ======================= fp16 GEMM: cp.async double-buffered =================
#define KC   64
#define SSTR 72
#define SM_A (128 * SSTR)
#define SM_B (64 * SSTR)
#define G_STAGE (SM_A + SM_B)                 // elems per stage
#define GEMM_SMEM (2 * G_STAGE * 2)           // 55296 B

__device__ __forceinline__ void gemm_mainloop(const __half* __restrict__ A,
                                              const __half* __restrict__ Bp,
                                              __half* smb,
                                              int rowBase, int colBase,
                                              float acc[4][4][4]) {
    const int tid  = threadIdx.x;
    const int lane = tid & 31;
    const int wid  = tid >> 5;
    const int wm   = wid >> 1;
    const int wn   = wid & 1;

    const uint32_t s0 = smem_u32(smb);

    const int r0 = tid >> 3;                  // 0..15
    const int cs = (tid & 7) * 8;
    const uint32_t dA = (uint32_t)(r0 * SSTR + cs) * 2;
    const uint32_t dB = (uint32_t)(SM_A + r0 * SSTR + cs) * 2;
    const __half* pA = A  + (size_t)(rowBase + r0) * D_ + cs;
    const __half* pB = Bp + (size_t)(colBase + r0) * D_ + cs;

    const int aRow = ((lane & 8) ? 8 : 0) + (lane & 7);
    const int aK   = ((lane & 16) ? 8 : 0);
    const int bRow = ((lane & 16) ? 8 : 0) + (lane & 7);
    const int bK   = ((lane & 8) ? 8 : 0);

    // issue stage 0
    {
        const uint32_t st = s0;
        #pragma unroll
        for (int u = 0; u < 8; u++)
            CP16(st + dA + (uint32_t)(u * 16 * SSTR) * 2, pA + (size_t)(u * 16) * D_);
        #pragma unroll
        for (int u = 0; u < 4; u++)
            CP16(st + dB + (uint32_t)(u * 16 * SSTR) * 2, pB + (size_t)(u * 16) * D_);
        CP_COMMIT();
    }

    for (int c = 0; c < 16; c++) {
        CP_WAIT0();
        __syncthreads();

        if (c + 1 < 16) {
            const uint32_t st = s0 + ((c + 1) & 1) * (G_STAGE * 2);
            const int kb = (c + 1) * KC;
            #pragma unroll
            for (int u = 0; u < 8; u++)
                CP16(st + dA + (uint32_t)(u * 16 * SSTR) * 2,
                     pA + (size_t)(u * 16) * D_ + kb);
            #pragma unroll
            for (int u = 0; u < 4; u++)
                CP16(st + dB + (uint32_t)(u * 16 * SSTR) * 2,
                     pB + (size_t)(u * 16) * D_ + kb);
            CP_COMMIT();
        }

        const uint32_t sA = s0 + (c & 1) * (G_STAGE * 2);
        const uint32_t sB = sA + SM_A * 2;

        #pragma unroll
        for (int k16 = 0; k16 < 4; k16++) {
            const int kk = k16 * 16;
            uint32_t bfr[4][2];
            #pragma unroll
            for (int g = 0; g < 2; g++) {
                const uint32_t off =
                    (uint32_t)((wn * 32 + g * 16 + bRow) * SSTR + kk + bK) * 2;
                uint32_t t4[4];
                ldsm_x4(t4, sB + off);
                bfr[2*g][0] = t4[0]; bfr[2*g][1] = t4[1];
                bfr[2*g+1][0] = t4[2]; bfr[2*g+1][1] = t4[3];
            }
            #pragma unroll
            for (int mi = 0; mi < 4; mi++) {
                const uint32_t offA =
                    (uint32_t)((wm * 64 + mi * 16 + aRow) * SSTR + kk + aK) * 2;
                uint32_t ah[4];
                ldsm_x4(ah, sA + offA);
                #pragma unroll
                for (int ni = 0; ni < 4; ni++)
                    mma16816(acc[mi][ni], ah, bfr[ni]);
            }
        }
        __syncthreads();
    }
}

// fused QKV + fused V-column-sum
__global__ void __launch_bounds__(128) qkv_gemm() {
    extern __shared__ __half smb[];
    const int rowBase = blockIdx.y * 128;
    const int colBase = blockIdx.x * 64;       // [0, 3072)
    const int z = colBase >> 10;               // 0=Q 1=K 2=V
    const int colLoc = colBase & 1023;
    __half* C = (z == 0) ? g_q : (z == 1) ? g_k : g_v;

    float acc[4][4][4];
    #pragma unroll
    for (int i = 0; i < 4; i++)
        #pragma unroll
        for (int j = 0; j < 4; j++)
            #pragma unroll
            for (int q = 0; q < 4; q++) acc[i][j][q] = 0.f;

    gemm_mainloop(g_x, g_w, smb, rowBase, colBase, acc);

    const int lane = threadIdx.x & 31;
    const int wid  = threadIdx.x >> 5;
    const int wm   = wid >> 1;
    const int wn   = wid & 1;
    const int qr = lane >> 2;
    const int qc = (lane & 3) * 2;
    #pragma unroll
    for (int mi = 0; mi < 4; mi++) {
        const int m0 = rowBase + wm * 64 + mi * 16 + qr;
        #pragma unroll
        for (int ni = 0; ni < 4; ni++) {
            const int cc = colLoc + wn * 32 + ni * 8 + qc;
            #pragma unroll
            for (int rr = 0; rr < 2; rr++) {
                const size_t o = (size_t)(m0 + rr * 8) * D_ + cc;
                *(__half2*)(C + o) = __floats2half2_rn(acc[mi][ni][rr*2+0],
                                                       acc[mi][ni][rr*2+1]);
            }
        }
    }

    if (z == 2) {
        const int b = rowBase >> 11;
        const int h = colLoc >> 6;
        #pragma unroll
        for (int ni = 0; ni < 4; ni++) {
            float c0 = 0.f, c1 = 0.f;
            #pragma unroll
            for (int mi = 0; mi < 4; mi++) {
                c0 += acc[mi][ni][0] + acc[mi][ni][2];
                c1 += acc[mi][ni][1] + acc[mi][ni][3];
            }
            c0 += __shfl_xor_sync(0xffffffffu, c0, 4);
            c0 += __shfl_xor_sync(0xffffffffu, c0, 8);
            c0 += __shfl_xor_sync(0xffffffffu, c0, 16);
            c1 += __shfl_xor_sync(0xffffffffu, c1, 4);
            c1 += __shfl_xor_sync(0xffffffffu, c1, 8);
            c1 += __shfl_xor_sync(0xffffffffu, c1, 16);
            if (qr == 0) {
                const int dd = wn * 32 + ni * 8 + qc;
                atomicAdd(&g_vsum[(b * H_ + h) * DK_ + dd], c0);
                atomicAdd(&g_vsum[(b * H_ + h) * DK_ + dd + 1], c1);
            }
        }
    }
}

// output projection with bias, fp32 out
__global__ void __launch_bounds__(128) out_gemm(const float* __restrict__ bias,
                                                float* __restrict__ C) {
    extern __shared__ __half smb[];
    const int rowBase = blockIdx.y * 128;
    const int colBase = blockIdx.x * 64;

    float acc[4][4][4];
    #pragma unroll
    for (int i = 0; i < 4; i++)
        #pragma unroll
        for (int j = 0; j < 4; j++)
            #pragma unroll
            for (int q = 0; q < 4; q++) acc[i][j][q] = 0.f;

    gemm_mainloop(g_c, g_w + 3 * (size_t)D_ * D_, smb, rowBase, colBase, acc);

    const int lane = threadIdx.x & 31;
    const int wid  = threadIdx.x >> 5;
    const int wm   = wid >> 1;
    const int wn   = wid & 1;
    const int qr = lane >> 2;
    const int qc = (lane & 3) * 2;
    #pragma unroll
    for (int mi = 0; mi < 4; mi++) {
        const int m0 = rowBase + wm * 64 + mi * 16 + qr;
        #pragma unroll
        for (int ni = 0; ni < 4; ni++) {
            const int cc = colBase + wn * 32 + ni * 8 + qc;
            float b0 = bias[cc], b1 = bias[cc + 1];
            float2 v0; v0.x = acc[mi][ni][0] + b0; v0.y = acc[mi][ni][1] + b1;
            float2 v1; v1.x = acc[mi][ni][2] + b0; v1.y = acc[mi][ni][3] + b1;
            *(float2*)&C[(size_t)m0 * D_ + cc] = v0;
            *(float2*)&C[(size_t)(m0 + 8) * D_ + cc] = v1;
        }
    }
}

// ======== flash attention: paired q-blocks + cp.async double-buffered K/V ====
#define FSC 0.180336880f
#define FS 72
#define F_T (64 * FS)                            // elems per 64x64 tile
#define FLASH_SMEM (5 * F_T * 2 + 2 * 64 * 4)    // Q + 2 KV stages + padf[2][64]

__global__ void __launch_bounds__(128) flash_mma(const int* __restrict__ kpm) {
    extern __shared__ __half fsm[];
    __half* Qs = fsm;
    float* padf = (float*)(fsm + 5 * F_T);       // [2][64]

    const int tid  = threadIdx.x;
    const int lane = tid & 31;
    const int wq   = tid >> 5;
    const int pair = blockIdx.x;                // 0..15
    const int bh   = blockIdx.y;
    const int b = bh / H_, h = bh % H_;

    const uint32_t sQ   = smem_u32(Qs);
    const uint32_t sKV0 = sQ + F_T * 2;
    const size_t headOff = (size_t)b * S_ * D_ + h * DK_;

    const int aRow = ((lane & 8) ? 8 : 0) + (lane & 7);
    const int aK   = ((lane & 16) ? 8 : 0);
    const int bRow = ((lane & 16) ? 8 : 0) + (lane & 7);
    const int bK   = ((lane & 8) ? 8 : 0);
    const int vRow = ((lane & 8) ? 8 : 0) + (lane & 7);
    const int vCol = ((lane & 16) ? 8 : 0);
    const int colq = (lane & 3) * 2;
    const float invS = 1.0f / (float)S_;

    const int fr = tid >> 3;
    const int fc = (tid & 7) * 8;
    const uint32_t fdst = (uint32_t)(fr * FS + fc) * 2;

    #pragma unroll 1
    for (int hf = 0; hf < 2; hf++) {
        const int qblk = (hf == 0) ? (31 - pair) : pair;
        const size_t qOff = headOff + (size_t)(qblk * 64) * D_;

        __syncthreads();
        #pragma unroll
        for (int u = 0; u < 4; u++) {
            const uint32_t d = fdst + (uint32_t)(u * 16 * FS) * 2;
            const size_t gq = qOff + (size_t)(fr + u * 16) * D_ + fc;
            CP16(sQ + d, g_q + gq);
            const size_t gk = headOff + (size_t)(fr + u * 16) * D_ + fc;
            CP16(sKV0 + d, g_k + gk);
            CP16(sKV0 + F_T * 2 + d, g_v + gk);
        }
        if (tid < 64) padf[tid] = kpm[b * S_ + tid] ? -INFINITY : 0.f;
        CP_COMMIT();

        float m0 = -INFINITY, m1 = -INFINITY, l0 = 0.f, l1 = 0.f;
        float oacc[8][4];
        #pragma unroll
        for (int ni = 0; ni < 8; ni++)
            #pragma unroll
            for (int q = 0; q < 4; q++) oacc[ni][q] = 0.f;

        const int qr0 = qblk * 64 + wq * 16 + (lane >> 2);
        const int qr1 = qr0 + 8;

        for (int kt = 0; kt <= qblk; kt++) {
            CP_WAIT0();
            __syncthreads();

            if (kt + 1 <= qblk) {
                const uint32_t st = sKV0 + ((kt + 1) & 1) * (2 * F_T * 2);
                const size_t kOff = headOff + (size_t)((kt + 1) * 64) * D_;
                #pragma unroll
                for (int u = 0; u < 4; u++) {
                    const uint32_t d = fdst + (uint32_t)(u * 16 * FS) * 2;
                    const size_t gk = kOff + (size_t)(fr + u * 16) * D_ + fc;
                    CP16(st + d, g_k + gk);
                    CP16(st + F_T * 2 + d, g_v + gk);
                }
                if (tid < 64)
                    padf[((kt + 1) & 1) * 64 + tid] =
                        kpm[b * S_ + (kt + 1) * 64 + tid] ? -INFINITY : 0.f;
                CP_COMMIT();
            }

            const uint32_t sK = sKV0 + (kt & 1) * (2 * F_T * 2);
            const uint32_t sV = sK + F_T * 2;
            const float* pd = padf + (kt & 1) * 64;

            float sacc[8][4];
            #pragma unroll
            for (int ni = 0; ni < 8; ni++)
                #pragma unroll
                for (int q = 0; q < 4; q++) sacc[ni][q] = 0.f;

            #pragma unroll
            for (int j = 0; j < 4; j++) {
                const int kk = j * 16;
                uint32_t ah[4];
                ldsm_x4(ah, sQ + (uint32_t)((wq * 16 + aRow) * FS + kk + aK) * 2);
                #pragma unroll
                for (int g = 0; g < 4; g++) {
                    const uint32_t off = (uint32_t)((g * 16 + bRow) * FS + kk + bK) * 2;
                    uint32_t th[4];
                    ldsm_x4(th, sK + off);
                    mma16816(sacc[2*g],   ah, th);
                    mma16816(sacc[2*g+1], ah, th + 2);
                }
            }

            const bool diag = (kt == qblk);
            #pragma unroll
            for (int ni = 0; ni < 8; ni++) {
                const float pj0 = pd[ni * 8 + colq];
                const float pj1 = pd[ni * 8 + colq + 1];
                sacc[ni][0] = fmaf(sacc[ni][0], FSC, pj0);
                sacc[ni][1] = fmaf(sacc[ni][1], FSC, pj1);
                sacc[ni][2] = fmaf(sacc[ni][2], FSC, pj0);
                sacc[ni][3] = fmaf(sacc[ni][3], FSC, pj1);
                if (diag) {
                    const int kc = kt * 64 + ni * 8 + colq;
                    if (kc     > qr0) sacc[ni][0] = -INFINITY;
                    if (kc + 1 > qr0) sacc[ni][1] = -INFINITY;
                    if (kc     > qr1) sacc[ni][2] = -INFINITY;
                    if (kc + 1 > qr1) sacc[ni][3] = -INFINITY;
                }
            }

            float mt0 = -INFINITY, mt1 = -INFINITY;
            #pragma unroll
            for (int ni = 0; ni < 8; ni++) {
                mt0 = fmaxf(mt0, fmaxf(sacc[ni][0], sacc[ni][1]));
                mt1 = fmaxf(mt1, fmaxf(sacc[ni][2], sacc[ni][3]));
            }
            mt0 = fmaxf(mt0, __shfl_xor_sync(0xffffffffu, mt0, 1));
            mt0 = fmaxf(mt0, __shfl_xor_sync(0xffffffffu, mt0, 2));
            mt1 = fmaxf(mt1, __shfl_xor_sync(0xffffffffu, mt1, 1));
            mt1 = fmaxf(mt1, __shfl_xor_sync(0xffffffffu, mt1, 2));

            const float mn0 = fmaxf(m0, mt0);
            const float mn1 = fmaxf(m1, mt1);
            const bool live0 = (mn0 != -INFINITY);
            const bool live1 = (mn1 != -INFINITY);
            const float alpha0 = live0 ? exp2f(m0 - mn0) : 1.f;
            const float alpha1 = live1 ? exp2f(m1 - mn1) : 1.f;

            float ps0 = 0.f, ps1 = 0.f;
            #pragma unroll
            for (int ni = 0; ni < 8; ni++) {
                float p00 = live0 ? exp2f(sacc[ni][0] - mn0) : 0.f;
                float p01 = live0 ? exp2f(sacc[ni][1] - mn0) : 0.f;
                float p10 = live1 ? exp2f(sacc[ni][2] - mn1) : 0.f;
                float p11 = live1 ? exp2f(sacc[ni][3] - mn1) : 0.f;
                sacc[ni][0] = p00; sacc[ni][1] = p01;
                sacc[ni][2] = p10; sacc[ni][3] = p11;
                ps0 += p00 + p01;
                ps1 += p10 + p11;
            }
            ps0 += __shfl_xor_sync(0xffffffffu, ps0, 1);
            ps0 += __shfl_xor_sync(0xffffffffu, ps0, 2);
            ps1 += __shfl_xor_sync(0xffffffffu, ps1, 1);
            ps1 += __shfl_xor_sync(0xffffffffu, ps1, 2);

            l0 = l0 * alpha0 + ps0;
            l1 = l1 * alpha1 + ps1;
            m0 = mn0; m1 = mn1;
            #pragma unroll
            for (int ni = 0; ni < 8; ni++) {
                oacc[ni][0] *= alpha0; oacc[ni][1] *= alpha0;
                oacc[ni][2] *= alpha1; oacc[ni][3] *= alpha1;
            }

            #pragma unroll
            for (int j = 0; j < 4; j++) {
                uint32_t af[4];
                #pragma unroll
                for (int t = 0; t < 2; t++) {
                    af[2*t]   = pack_h2(sacc[2*j+t][0], sacc[2*j+t][1]);
                    af[2*t+1] = pack_h2(sacc[2*j+t][2], sacc[2*j+t][3]);
                }
                #pragma unroll
                for (int g = 0; g < 4; g++) {
                    const uint32_t off =
                        (uint32_t)((j * 16 + vRow) * FS + g * 16 + vCol) * 2;
                    uint32_t vb[4];
                    ldsm_x4_t(vb, sV + off);
                    mma16816(oacc[2*g],   af, vb);
                    mma16816(oacc[2*g+1], af, vb + 2);
                }
            }
        }

        const bool dead0 = (m0 == -INFINITY);
        const bool dead1 = (m1 == -INFINITY);
        const float inv0 = dead0 ? 0.f : 1.0f / l0;
        const float inv1 = dead1 ? 0.f : 1.0f / l1;
        const size_t row0 = (size_t)b * S_ + qr0;
        const size_t row1 = (size_t)b * S_ + qr1;
        #pragma unroll
        for (int ni = 0; ni < 8; ni++) {
            const int dd = ni * 8 + colq;
            float v00, v01, v10, v11;
            if (dead0) {
                v00 = g_vsum[bh * DK_ + dd] * invS;
                v01 = g_vsum[bh * DK_ + dd + 1] * invS;
            } else { v00 = oacc[ni][0] * inv0; v01 = oacc[ni][1] * inv0; }
            if (dead1) {
                v10 = g_vsum[bh * DK_ + dd] * invS;
                v11 = g_vsum[bh * DK_ + dd + 1] * invS;
            } else { v10 = oacc[ni][2] * inv1; v11 = oacc[ni][3] * inv1; }

            const size_t o0 = row0 * D_ + h * DK_ + dd;
            const size_t o1 = row1 * D_ + h * DK_ + dd;
            *(__half2*)(g_c + o0) = __floats2half2_rn(v00, v01);
            *(__half2*)(g_c + o1) = __floats2half2_rn(v10, v11);
        }
    }
}

// ---------------- launch ------------------------------------------------------
extern "C" void kernel_launch(void* const* d_in, const int* in_sizes, int n_in,
                              void* d_out, int out_size) {
    const float* x   = (const float*)d_in[0];
    const int*   kpm = (const int*)d_in[2];
    const float* Wq  = (const float*)d_in[3];
    const float* Wk  = (const float*)d_in[4];
    const float* Wv  = (const float*)d_in[5];
    const float* Wo  = (const float*)d_in[6];
    const float* bo  = (const float*)d_in[7];
    float* out = (float*)d_out;

    __half *xh, *wh;
    float* vsum;
    cudaGetSymbolAddress((void**)&xh, g_x);
    cudaGetSymbolAddress((void**)&wh, g_w);
    cudaGetSymbolAddress((void**)&vsum, g_vsum);

    cudaFuncSetAttribute(qkv_gemm, cudaFuncAttributeMaxDynamicSharedMemorySize, GEMM_SMEM);
    cudaFuncSetAttribute(out_gemm, cudaFuncAttributeMaxDynamicSharedMemorySize, GEMM_SMEM);
    cudaFuncSetAttribute(flash_mma, cudaFuncAttributeMaxDynamicSharedMemorySize, FLASH_SMEM);

    // 0) zero vsum (capture-safe async memset)
    cudaMemsetAsync(vsum, 0, B_ * H_ * DK_ * sizeof(float));

    // 1) convert x to fp16
    convert_kernel<<<(MROWS * D_ / 4) / 256, 256>>>(x, xh);

    // 2) transpose all four weights in one launch
    dim3 tb(32, 8), tg(32, 32, 4);
    transpose_kernel<<<tg, tb>>>(Wq, Wk, Wv, Wo, wh);

    // 3) fused Q/K/V projections + V column sums (double-buffered)
    dim3 gq(3 * D_ / 64, MROWS / 128);   // (48, 32)
    qkv_gemm<<<gq, 128, GEMM_SMEM>>>();

    // 4) flash attention: paired q-blocks + double-buffered K/V
    dim3 fg(S_ / 128, B_ * H_);          // (16, 32)
    flash_mma<<<fg, 128, FLASH_SMEM>>>(kpm);

    // 5) output projection with bias (fp32 out, double-buffered)
    dim3 gg(D_ / 64, MROWS / 128);       // (16, 32)
    out_gemm<<<gg, 128, GEMM_SMEM>>>(bo, out);
}